// round 5
// baseline (speedup 1.0000x reference)
#include <cuda_runtime.h>
#include <cuda_bf16.h>
#include <math.h>
#include <stdint.h>

// Problem constants
#define Bn 4
#define Tn 2048
#define Dn 1024
#define Hn 16
#define HDn 64
#define QKV_STRIDE (Bn * Hn * Tn * HDn)   // 8388608 elems per q/k/v

// ---------------------------------------------------------------------------
// Device scratch (no cudaMalloc allowed)
// ---------------------------------------------------------------------------
__device__ unsigned short qkvh[3ull * QKV_STRIDE];      // [3][B][H][T][HD] bf16 hi
__device__ unsigned short qkvl[3ull * QKV_STRIDE];      // bf16 lo
__device__ unsigned short xa_hi[(size_t)Bn * Tn * Dn];  // x split [8192][1024]
__device__ unsigned short xa_lo[(size_t)Bn * Tn * Dn];
__device__ unsigned short wq_hi[(size_t)3 * Dn * Dn];   // Wqkv split (native K-major)
__device__ unsigned short wq_lo[(size_t)3 * Dn * Dn];
__device__ unsigned short wo_hi[(size_t)Dn * Dn];       // Wout split
__device__ unsigned short wo_lo[(size_t)Dn * Dn];
__device__ unsigned short ga_hi[(size_t)Bn * Tn * Dn];  // attention out split
__device__ unsigned short ga_lo[(size_t)Bn * Tn * Dn];

// ---------------------------------------------------------------------------
// PTX helpers (non-arch-suffixed; valid on plain sm_103 target)
// ---------------------------------------------------------------------------
__device__ __forceinline__ uint32_t s2u(const void* p) {
    uint32_t a;
    asm("{ .reg .u64 t; cvta.to.shared.u64 t, %1; cvt.u32.u64 %0, t; }"
        : "=r"(a) : "l"(p));
    return a;
}
__device__ __forceinline__ void cpa16(uint32_t d, const void* s) {
    asm volatile("cp.async.cg.shared.global [%0], [%1], 16;"
                 :: "r"(d), "l"(s) : "memory");
}
__device__ __forceinline__ void cpa_commit() {
    asm volatile("cp.async.commit_group;" ::: "memory");
}
template<int N>
__device__ __forceinline__ void cpa_wait() {
    asm volatile("cp.async.wait_group %0;" :: "n"(N) : "memory");
}
__device__ __forceinline__ void ldsm4(uint32_t* r, uint32_t a) {
    asm volatile("ldmatrix.sync.aligned.m8n8.x4.shared.b16 {%0,%1,%2,%3}, [%4];"
        : "=r"(r[0]), "=r"(r[1]), "=r"(r[2]), "=r"(r[3]) : "r"(a));
}
__device__ __forceinline__ void ldsm4t(uint32_t* r, uint32_t a) {
    asm volatile("ldmatrix.sync.aligned.m8n8.x4.trans.shared.b16 {%0,%1,%2,%3}, [%4];"
        : "=r"(r[0]), "=r"(r[1]), "=r"(r[2]), "=r"(r[3]) : "r"(a));
}
__device__ __forceinline__ void mma16816(float* d, const uint32_t* a, const uint32_t* b) {
    asm volatile(
        "mma.sync.aligned.m16n8k16.row.col.f32.bf16.bf16.f32 "
        "{%0,%1,%2,%3}, {%4,%5,%6,%7}, {%8,%9}, {%0,%1,%2,%3};"
        : "+f"(d[0]), "+f"(d[1]), "+f"(d[2]), "+f"(d[3])
        : "r"(a[0]), "r"(a[1]), "r"(a[2]), "r"(a[3]), "r"(b[0]), "r"(b[1]));
}
__device__ __forceinline__ uint32_t pack_bf2(float lo, float hi) {
    uint32_t d;
    asm("cvt.rn.bf16x2.f32 %0, %1, %2;" : "=r"(d) : "f"(hi), "f"(lo));
    return d;
}

// Swizzles
#define SWA(o) ((o) ^ ((((o) >> 7) & 3) << 4))   // 64B rows (GEMM A buf)
#define SWB(o) ((o) ^ ((((o) >> 8) & 7) << 4))   // 256B rows (GEMM B buf)
#define SW128(o) ((o) ^ ((((o) >> 7) & 7) << 4)) // 128B rows (attention)

// ---------------------------------------------------------------------------
// fp32 -> (bf16 hi, bf16 lo)
// ---------------------------------------------------------------------------
__device__ __forceinline__ void split1(float v, unsigned short& h, unsigned short& l) {
    __nv_bfloat16 hb = __float2bfloat16(v);
    float r = v - __bfloat162float(hb);
    __nv_bfloat16 lb = __float2bfloat16(r);
    h = reinterpret_cast<unsigned short&>(hb);
    l = reinterpret_cast<unsigned short&>(lb);
}

__global__ __launch_bounds__(256)
void split_kernel(const float* __restrict__ in, unsigned short* __restrict__ hi,
                  unsigned short* __restrict__ lo, int n4)
{
    int i = blockIdx.x * 256 + threadIdx.x;
    if (i >= n4) return;
    float4 v = ((const float4*)in)[i];
    ushort4 h, l;
    split1(v.x, h.x, l.x);
    split1(v.y, h.y, l.y);
    split1(v.z, h.z, l.z);
    split1(v.w, h.w, l.w);
    ((ushort4*)hi)[i] = h;
    ((ushort4*)lo)[i] = l;
}

// ---------------------------------------------------------------------------
// bf16x3 GEMM via mma.sync: D[8192][NN] = A[8192][1024] @ B[1024][NN]
// 256x128 CTA tile, BK=32, 3-stage cp.async pipeline, 8 warps (4m x 2n),
// warp tile 64x64 (4 m16 x 8 n8).
// MODE 0: split fp32 acc -> qkvh/qkvl scatter.  MODE 1: fp32 write to Cout.
// ---------------------------------------------------------------------------
#define BK 32
#define NKB2 32
#define STAGES 3
#define ABUF 16384               // 256 x 32 bf16
#define BBUF 8192                // 32 x 128 bf16
#define STG_BYTES (2 * ABUF + 2 * BBUF)   // 49152

template<int MODE, int NN>
__global__ __launch_bounds__(256)
void tc_gemm(const unsigned short* __restrict__ Ah, const unsigned short* __restrict__ Al,
             const unsigned short* __restrict__ Bh, const unsigned short* __restrict__ Bl,
             float* __restrict__ Cout)
{
    extern __shared__ __align__(1024) unsigned char gsm[];
    const uint32_t sbase = s2u(gsm);
    const int tid = threadIdx.x;
    const int lane = tid & 31, wid = tid >> 5;
    const int wm = wid & 3, wn = wid >> 2;           // 4(m) x 2(n)
    const int bm = blockIdx.y * 256, bn = blockIdx.x * 128;

    const unsigned short* Abases[2] = { Ah + (size_t)bm * 1024, Al + (size_t)bm * 1024 };
    const unsigned short* Bbases[2] = { Bh + bn, Bl + bn };

    // per stage: A 2x1024 chunks, B 2x512 chunks; coalesced id = i*256 + tid
    auto load_stage = [&](int st, int kb) {
        uint32_t sb = sbase + st * STG_BYTES;
#pragma unroll
        for (int sp = 0; sp < 2; sp++) {
#pragma unroll
            for (int i = 0; i < 4; i++) {
                int id = i * 256 + tid;          // 0..1023
                int r = id >> 2, c = id & 3;
                cpa16(sb + sp * ABUF + SWA(r * 64 + c * 16),
                      Abases[sp] + (size_t)r * 1024 + kb * BK + c * 8);
            }
#pragma unroll
            for (int i = 0; i < 2; i++) {
                int id = i * 256 + tid;          // 0..511
                int rk = id >> 4, cc = id & 15;
                cpa16(sb + 2 * ABUF + sp * BBUF + SWB(rk * 256 + cc * 16),
                      Bbases[sp] + (size_t)(kb * BK + rk) * NN + cc * 8);
            }
        }
    };

    float acc[4][8][4];
#pragma unroll
    for (int mt = 0; mt < 4; mt++)
#pragma unroll
        for (int nt = 0; nt < 8; nt++)
#pragma unroll
            for (int q = 0; q < 4; q++) acc[mt][nt][q] = 0.f;

    load_stage(0, 0); cpa_commit();
    load_stage(1, 1); cpa_commit();

    const int a_lr = lane & 15;
    const int a_hk = (lane >> 4) << 4;

    for (int kb = 0; kb < NKB2; kb++) {
        const int cur = kb % STAGES;
        if (kb >= NKB2 - 2) cpa_wait<0>(); else cpa_wait<1>();
        __syncthreads();

        uint32_t sb = sbase + cur * STG_BYTES;
#pragma unroll
        for (int ks = 0; ks < 2; ks++) {
            // B fragments first (reused by all 4 m-tiles)
            uint32_t bfr[2][8][2];
#pragma unroll
            for (int sp = 0; sp < 2; sp++)
#pragma unroll
                for (int nt2 = 0; nt2 < 4; nt2++) {
                    int kk = ks * 16 + a_lr;
                    int nb = wn * 128 + nt2 * 32 + a_hk;
                    uint32_t t[4];
                    ldsm4t(t, sb + 2 * ABUF + sp * BBUF + SWB(kk * 256 + nb));
                    bfr[sp][nt2 * 2][0] = t[0]; bfr[sp][nt2 * 2][1] = t[1];
                    bfr[sp][nt2 * 2 + 1][0] = t[2]; bfr[sp][nt2 * 2 + 1][1] = t[3];
                }
#pragma unroll
            for (int mt = 0; mt < 4; mt++) {
                uint32_t afh[4], afl[4];
                int r = wm * 64 + mt * 16 + a_lr;
                ldsm4(afh, sb + SWA(r * 64 + ks * 32 + a_hk));
                ldsm4(afl, sb + ABUF + SWA(r * 64 + ks * 32 + a_hk));
#pragma unroll
                for (int nt = 0; nt < 8; nt++) {
                    mma16816(acc[mt][nt], afh, bfr[0][nt]);
                    mma16816(acc[mt][nt], afh, bfr[1][nt]);
                    mma16816(acc[mt][nt], afl, bfr[0][nt]);
                }
            }
        }
        __syncthreads();
        if (kb + STAGES - 1 < NKB2) {
            load_stage((kb + STAGES - 1) % STAGES, kb + STAGES - 1);
            cpa_commit();
        }
    }

    const int gid = lane >> 2, tg = lane & 3;
#pragma unroll
    for (int mt = 0; mt < 4; mt++)
#pragma unroll
        for (int nt = 0; nt < 8; nt++) {
            int row0 = bm + wm * 64 + mt * 16 + gid;
            int col = bn + wn * 64 + nt * 8 + tg * 2;
#pragma unroll
            for (int half = 0; half < 2; half++) {
                int row = row0 + half * 8;
                float v0 = acc[mt][nt][half * 2], v1 = acc[mt][nt][half * 2 + 1];
                if (MODE == 0) {
                    int s = col >> 10, h = (col >> 6) & 15, d = col & 63;
                    int b = row >> 11, t = row & 2047;
                    size_t idx = (size_t)s * QKV_STRIDE +
                                 (((size_t)(b * Hn + h) * Tn + t) << 6) + d;
                    unsigned short h0, l0, h1, l1;
                    split1(v0, h0, l0);
                    split1(v1, h1, l1);
                    *(uint32_t*)&qkvh[idx] = (uint32_t)h0 | ((uint32_t)h1 << 16);
                    *(uint32_t*)&qkvl[idx] = (uint32_t)l0 | ((uint32_t)l1 << 16);
                } else {
                    *(float2*)&Cout[(size_t)row * NN + col] = make_float2(v0, v1);
                }
            }
        }
}

// ---------------------------------------------------------------------------
// Tensor-core flash attention (bf16x3 QK^T and PV, fp32 accum).
// 128 threads = 4 warps, each warp owns 16 q rows; block = 64 q rows of (b,h).
// ---------------------------------------------------------------------------
#define AQ_OFF 0            // Q hi 8KB
#define AQL_OFF 8192        // Q lo 8KB
#define AKV_OFF 16384       // 2 stages x (Kh,Kl,Vh,Vl) 8KB each
#define APOS_OFF (16384 + 65536)
#define ATTN_SMEM_SZ (16384 + 65536 + 512)

__global__ __launch_bounds__(128)
void attn_mma(const int* __restrict__ pos)
{
    extern __shared__ __align__(1024) unsigned char am[];
    const uint32_t sb = s2u(am);
    const int tid = threadIdx.x, lane = tid & 31, wm = tid >> 5;
    const int b = blockIdx.y >> 4, h = blockIdx.y & 15;
    const int i0 = blockIdx.x * 64;

    const size_t bh_off = ((size_t)(b * Hn + h) * Tn) << 6;
    const unsigned short* Qhg = qkvh + bh_off + ((size_t)i0 << 6);
    const unsigned short* Qlg = qkvl + bh_off + ((size_t)i0 << 6);
    const unsigned short* Khg = qkvh + (size_t)QKV_STRIDE + bh_off;
    const unsigned short* Klg = qkvl + (size_t)QKV_STRIDE + bh_off;
    const unsigned short* Vhg = qkvh + 2ull * QKV_STRIDE + bh_off;
    const unsigned short* Vlg = qkvl + 2ull * QKV_STRIDE + bh_off;
    const int* posb = pos + b * Tn;

#pragma unroll
    for (int i = 0; i < 4; i++) {
        int id = tid + i * 128;
        int r = id >> 3, c = id & 7;
        cpa16(sb + AQ_OFF + SW128(r * 128 + c * 16), Qhg + (size_t)r * 64 + c * 8);
        cpa16(sb + AQL_OFF + SW128(r * 128 + c * 16), Qlg + (size_t)r * 64 + c * 8);
    }
    cpa_commit();

    auto load_kv = [&](int st, int j0) {
        uint32_t base = sb + AKV_OFF + st * 32768;
        const unsigned short* srcs[4] = {
            Khg + ((size_t)j0 << 6), Klg + ((size_t)j0 << 6),
            Vhg + ((size_t)j0 << 6), Vlg + ((size_t)j0 << 6) };
#pragma unroll
        for (int buf = 0; buf < 4; buf++)
#pragma unroll
            for (int i = 0; i < 4; i++) {
                int id = tid + i * 128;
                int r = id >> 3, c = id & 7;
                cpa16(base + buf * 8192 + SW128(r * 128 + c * 16),
                      srcs[buf] + (size_t)r * 64 + c * 8);
            }
        if (tid < 16)
            cpa16(sb + APOS_OFF + st * 256 + tid * 16, posb + j0 + tid * 4);
    };

    load_kv(0, 0);
    cpa_commit();

    cpa_wait<1>();
    __syncthreads();
    const int a_lr = lane & 15, a_hk = (lane >> 4) << 4;
    uint32_t qfh[4][4], qfl[4][4];
#pragma unroll
    for (int ks = 0; ks < 4; ks++) {
        int r = wm * 16 + a_lr;
        ldsm4(qfh[ks], sb + AQ_OFF + SW128(r * 128 + ks * 32 + a_hk));
        ldsm4(qfl[ks], sb + AQL_OFF + SW128(r * 128 + ks * 32 + a_hk));
    }

    const int pq0 = posb[i0 + wm * 16 + (lane >> 2)];
    const int pq1 = posb[i0 + wm * 16 + (lane >> 2) + 8];
    const int pqmax = posb[i0 + 63];
    const int jcol = 2 * (lane & 3);

    float m0 = -3e38f, m1 = -3e38f, l0 = 0.f, l1 = 0.f;
    float oacc[8][4];
#pragma unroll
    for (int nt = 0; nt < 8; nt++)
#pragma unroll
        for (int q = 0; q < 4; q++) oacc[nt][q] = 0.f;

    const float CS = 0.18033688011112042f;   // 0.125 * log2(e)

    int jb = 0, st = 0;
    for (;;) {
        int next = jb + 64;
        bool hn = (next < Tn) && (posb[next] <= pqmax);
        if (hn) { load_kv(st ^ 1, next); cpa_commit(); }
        if (hn) cpa_wait<1>(); else cpa_wait<0>();
        __syncthreads();

        const uint32_t kb_ = sb + AKV_OFF + st * 32768;
        const int* pkp = (const int*)(am + APOS_OFF + st * 256);

        float sacc[8][4];
#pragma unroll
        for (int nt = 0; nt < 8; nt++)
#pragma unroll
            for (int q = 0; q < 4; q++) sacc[nt][q] = 0.f;

#pragma unroll
        for (int ks = 0; ks < 4; ks++) {
            uint32_t kfh[4][4], kfl[4][4];
            const int g = lane >> 3;
            const int krow = (g >> 1) * 8 + (lane & 7);
            const int kchk = ks * 32 + (g & 1) * 16;
#pragma unroll
            for (int call = 0; call < 4; call++) {
                uint32_t off = SW128((call * 16 + krow) * 128 + kchk);
                ldsm4(kfh[call], kb_ + off);
                ldsm4(kfl[call], kb_ + 8192 + off);
            }
#pragma unroll
            for (int nt = 0; nt < 8; nt++) {
                const int c = nt >> 1, hf = (nt & 1) * 2;
                mma16816(sacc[nt], qfh[ks], &kfh[c][hf]);
                mma16816(sacc[nt], qfh[ks], &kfl[c][hf]);
                mma16816(sacc[nt], qfl[ks], &kfh[c][hf]);
            }
        }

        float mx0 = m0, mx1 = m1;
#pragma unroll
        for (int nt = 0; nt < 8; nt++) {
            int pk0 = pkp[nt * 8 + jcol], pk1 = pkp[nt * 8 + jcol + 1];
            float v0 = (pq0 < pk0) ? -3e38f : sacc[nt][0] * CS;
            float v1 = (pq0 < pk1) ? -3e38f : sacc[nt][1] * CS;
            float v2 = (pq1 < pk0) ? -3e38f : sacc[nt][2] * CS;
            float v3 = (pq1 < pk1) ? -3e38f : sacc[nt][3] * CS;
            sacc[nt][0] = v0; sacc[nt][1] = v1;
            sacc[nt][2] = v2; sacc[nt][3] = v3;
            mx0 = fmaxf(mx0, fmaxf(v0, v1));
            mx1 = fmaxf(mx1, fmaxf(v2, v3));
        }
        mx0 = fmaxf(mx0, __shfl_xor_sync(0xffffffffu, mx0, 1));
        mx0 = fmaxf(mx0, __shfl_xor_sync(0xffffffffu, mx0, 2));
        mx1 = fmaxf(mx1, __shfl_xor_sync(0xffffffffu, mx1, 1));
        mx1 = fmaxf(mx1, __shfl_xor_sync(0xffffffffu, mx1, 2));
        float al0 = exp2f(m0 - mx0), al1 = exp2f(m1 - mx1);
        m0 = mx0; m1 = mx1;

        float s0 = 0.f, s1 = 0.f;
#pragma unroll
        for (int nt = 0; nt < 8; nt++) {
            float p0 = exp2f(sacc[nt][0] - mx0);
            float p1 = exp2f(sacc[nt][1] - mx0);
            float p2 = exp2f(sacc[nt][2] - mx1);
            float p3 = exp2f(sacc[nt][3] - mx1);
            sacc[nt][0] = p0; sacc[nt][1] = p1;
            sacc[nt][2] = p2; sacc[nt][3] = p3;
            s0 += p0 + p1; s1 += p2 + p3;
        }
        s0 += __shfl_xor_sync(0xffffffffu, s0, 1);
        s0 += __shfl_xor_sync(0xffffffffu, s0, 2);
        s1 += __shfl_xor_sync(0xffffffffu, s1, 1);
        s1 += __shfl_xor_sync(0xffffffffu, s1, 2);
        l0 = l0 * al0 + s0;
        l1 = l1 * al1 + s1;
#pragma unroll
        for (int nt = 0; nt < 8; nt++) {
            oacc[nt][0] *= al0; oacc[nt][1] *= al0;
            oacc[nt][2] *= al1; oacc[nt][3] *= al1;
        }

        const uint32_t vb = kb_ + 16384;
#pragma unroll
        for (int kt = 0; kt < 4; kt++) {
            uint32_t ph[4], pl[4];
#pragma unroll
            for (int q = 0; q < 4; q++) {
                const float* src = (q < 2) ? sacc[2 * kt] : sacc[2 * kt + 1];
                float a = src[(q & 1) * 2], c = src[(q & 1) * 2 + 1];
                uint32_t hp = pack_bf2(a, c);
                ph[q] = hp;
                float hl = __uint_as_float(hp << 16);
                float hh = __uint_as_float(hp & 0xFFFF0000u);
                pl[q] = pack_bf2(a - hl, c - hh);
            }
            uint32_t vfh[4][4], vfl[4][4];
#pragma unroll
            for (int call = 0; call < 4; call++) {
                uint32_t off = SW128((kt * 16 + a_lr) * 128 + call * 32 + a_hk);
                ldsm4t(vfh[call], vb + off);
                ldsm4t(vfl[call], vb + 8192 + off);
            }
#pragma unroll
            for (int nt = 0; nt < 8; nt++) {
                const int c = nt >> 1, hf = (nt & 1) * 2;
                mma16816(oacc[nt], ph, &vfh[c][hf]);
                mma16816(oacc[nt], ph, &vfl[c][hf]);
                mma16816(oacc[nt], pl, &vfh[c][hf]);
            }
        }

        __syncthreads();
        if (!hn) break;
        jb = next; st ^= 1;
    }

    float inv0 = 1.f / l0, inv1 = 1.f / l1;
    int t0r = i0 + wm * 16 + (lane >> 2);
#pragma unroll
    for (int nt = 0; nt < 8; nt++) {
        int col = h * 64 + nt * 8 + jcol;
#pragma unroll
        for (int half = 0; half < 2; half++) {
            int t = t0r + half * 8;
            float inv = half ? inv1 : inv0;
            float v0 = oacc[nt][half * 2] * inv;
            float v1 = oacc[nt][half * 2 + 1] * inv;
            unsigned short h0, lw0, h1, lw1;
            split1(v0, h0, lw0);
            split1(v1, h1, lw1);
            size_t idx = ((size_t)b * Tn + t) * Dn + col;
            *(uint32_t*)&ga_hi[idx] = (uint32_t)h0 | ((uint32_t)h1 << 16);
            *(uint32_t*)&ga_lo[idx] = (uint32_t)lw0 | ((uint32_t)lw1 << 16);
        }
    }
}

// ---------------------------------------------------------------------------
extern "C" void kernel_launch(void* const* d_in, const int* in_sizes, int n_in,
                              void* d_out, int out_size)
{
    const float* x   = (const float*)d_in[0];
    const int*   pos = (const int*)d_in[1];
    const float* Wq  = (const float*)d_in[2];
    const float* Wo  = (const float*)d_in[3];
    float* out = (float*)d_out;

    unsigned short *p_xh, *p_xl, *p_wqh, *p_wql, *p_woh, *p_wol, *p_gah, *p_gal;
    cudaGetSymbolAddress((void**)&p_xh,  xa_hi);
    cudaGetSymbolAddress((void**)&p_xl,  xa_lo);
    cudaGetSymbolAddress((void**)&p_wqh, wq_hi);
    cudaGetSymbolAddress((void**)&p_wql, wq_lo);
    cudaGetSymbolAddress((void**)&p_woh, wo_hi);
    cudaGetSymbolAddress((void**)&p_wol, wo_lo);
    cudaGetSymbolAddress((void**)&p_gah, ga_hi);
    cudaGetSymbolAddress((void**)&p_gal, ga_lo);

    const int GEMM_SMEM = STAGES * STG_BYTES;   // 147456

    // 0) bf16 hi/lo splits
    int n4x = (Bn * Tn * Dn) / 4;
    split_kernel<<<(n4x + 255) / 256, 256>>>(x, p_xh, p_xl, n4x);
    int n4wq = (3 * Dn * Dn) / 4;
    split_kernel<<<(n4wq + 255) / 256, 256>>>(Wq, p_wqh, p_wql, n4wq);
    int n4wo = (Dn * Dn) / 4;
    split_kernel<<<(n4wo + 255) / 256, 256>>>(Wo, p_woh, p_wol, n4wo);

    // 1) QKV projection -> qkvh/qkvl (bf16 hi/lo, scattered)
    cudaFuncSetAttribute(tc_gemm<0, 3072>,
                         cudaFuncAttributeMaxDynamicSharedMemorySize, GEMM_SMEM);
    tc_gemm<0, 3072><<<dim3(24, 32), 256, GEMM_SMEM>>>(p_xh, p_xl, p_wqh, p_wql, nullptr);

    // 2) tensor-core flash attention -> ga_hi/ga_lo
    cudaFuncSetAttribute(attn_mma,
                         cudaFuncAttributeMaxDynamicSharedMemorySize, ATTN_SMEM_SZ);
    attn_mma<<<dim3(Tn / 64, Bn * Hn), 128, ATTN_SMEM_SZ>>>(pos);

    // 3) output projection -> d_out
    cudaFuncSetAttribute(tc_gemm<1, 1024>,
                         cudaFuncAttributeMaxDynamicSharedMemorySize, GEMM_SMEM);
    tc_gemm<1, 1024><<<dim3(8, 32), 256, GEMM_SMEM>>>(p_gah, p_gal, p_woh, p_wol, out);
}

// round 6
// speedup vs baseline: 1.0855x; 1.0855x over previous
#include <cuda_runtime.h>
#include <cuda_bf16.h>
#include <math.h>
#include <stdint.h>

// Problem constants
#define Bn 4
#define Tn 2048
#define Dn 1024
#define Hn 16
#define HDn 64
#define QKV_STRIDE (Bn * Hn * Tn * HDn)   // 8388608 elems per q/k/v

// ---------------------------------------------------------------------------
// Device scratch (no cudaMalloc allowed)
// ---------------------------------------------------------------------------
__device__ unsigned short qkvh[3ull * QKV_STRIDE];      // [3][B][H][T][HD] bf16 hi
__device__ unsigned short qkvl[3ull * QKV_STRIDE];      // bf16 lo
__device__ unsigned short xa_hi[(size_t)Bn * Tn * Dn];  // x split [8192][1024]
__device__ unsigned short xa_lo[(size_t)Bn * Tn * Dn];
__device__ unsigned short wq_hi[(size_t)3 * Dn * Dn];   // Wqkv split (native K-major)
__device__ unsigned short wq_lo[(size_t)3 * Dn * Dn];
__device__ unsigned short wo_hi[(size_t)Dn * Dn];       // Wout split
__device__ unsigned short wo_lo[(size_t)Dn * Dn];
__device__ unsigned short ga_hi[(size_t)Bn * Tn * Dn];  // attention out split
__device__ unsigned short ga_lo[(size_t)Bn * Tn * Dn];

// ---------------------------------------------------------------------------
// PTX helpers (non-arch-suffixed; valid on plain sm_103 target)
// ---------------------------------------------------------------------------
__device__ __forceinline__ uint32_t s2u(const void* p) {
    uint32_t a;
    asm("{ .reg .u64 t; cvta.to.shared.u64 t, %1; cvt.u32.u64 %0, t; }"
        : "=r"(a) : "l"(p));
    return a;
}
__device__ __forceinline__ void cpa16(uint32_t d, const void* s) {
    asm volatile("cp.async.cg.shared.global [%0], [%1], 16;"
                 :: "r"(d), "l"(s) : "memory");
}
__device__ __forceinline__ void cpa_commit() {
    asm volatile("cp.async.commit_group;" ::: "memory");
}
template<int N>
__device__ __forceinline__ void cpa_wait() {
    asm volatile("cp.async.wait_group %0;" :: "n"(N) : "memory");
}
__device__ __forceinline__ void ldsm4(uint32_t* r, uint32_t a) {
    asm volatile("ldmatrix.sync.aligned.m8n8.x4.shared.b16 {%0,%1,%2,%3}, [%4];"
        : "=r"(r[0]), "=r"(r[1]), "=r"(r[2]), "=r"(r[3]) : "r"(a));
}
__device__ __forceinline__ void ldsm4t(uint32_t* r, uint32_t a) {
    asm volatile("ldmatrix.sync.aligned.m8n8.x4.trans.shared.b16 {%0,%1,%2,%3}, [%4];"
        : "=r"(r[0]), "=r"(r[1]), "=r"(r[2]), "=r"(r[3]) : "r"(a));
}
__device__ __forceinline__ void mma16816(float* d, const uint32_t* a, const uint32_t* b) {
    asm volatile(
        "mma.sync.aligned.m16n8k16.row.col.f32.bf16.bf16.f32 "
        "{%0,%1,%2,%3}, {%4,%5,%6,%7}, {%8,%9}, {%0,%1,%2,%3};"
        : "+f"(d[0]), "+f"(d[1]), "+f"(d[2]), "+f"(d[3])
        : "r"(a[0]), "r"(a[1]), "r"(a[2]), "r"(a[3]), "r"(b[0]), "r"(b[1]));
}
__device__ __forceinline__ uint32_t pack_bf2(float lo, float hi) {
    uint32_t d;
    asm("cvt.rn.bf16x2.f32 %0, %1, %2;" : "=r"(d) : "f"(hi), "f"(lo));
    return d;
}

// Swizzles
#define SWA(o) ((o) ^ ((((o) >> 7) & 3) << 4))   // 64B rows (GEMM A buf)
#define SWB(o) ((o) ^ ((((o) >> 8) & 7) << 4))   // 256B rows (GEMM B buf)
#define SW128(o) ((o) ^ ((((o) >> 7) & 7) << 4)) // 128B rows (attention)

// ---------------------------------------------------------------------------
// fp32 -> (bf16 hi, bf16 lo)
// ---------------------------------------------------------------------------
__device__ __forceinline__ void split1(float v, unsigned short& h, unsigned short& l) {
    __nv_bfloat16 hb = __float2bfloat16(v);
    float r = v - __bfloat162float(hb);
    __nv_bfloat16 lb = __float2bfloat16(r);
    h = reinterpret_cast<unsigned short&>(hb);
    l = reinterpret_cast<unsigned short&>(lb);
}

__global__ __launch_bounds__(256)
void split_kernel(const float* __restrict__ in, unsigned short* __restrict__ hi,
                  unsigned short* __restrict__ lo, int n4)
{
    int i = blockIdx.x * 256 + threadIdx.x;
    if (i >= n4) return;
    float4 v = ((const float4*)in)[i];
    ushort4 h, l;
    split1(v.x, h.x, l.x);
    split1(v.y, h.y, l.y);
    split1(v.z, h.z, l.z);
    split1(v.w, h.w, l.w);
    ((ushort4*)hi)[i] = h;
    ((ushort4*)lo)[i] = l;
}

// ---------------------------------------------------------------------------
// bf16x3 GEMM via mma.sync: D[8192][NN] = A[8192][1024] @ B[1024][NN]
// 128x128 CTA tile, BK=32, 3-stage cp.async pipeline, 8 warps (4m x 2n),
// warp tile 32x64.  ONE sync per k-block.
// MODE 0: split fp32 acc -> qkvh/qkvl scatter.  MODE 1: fp32 write to Cout.
// ---------------------------------------------------------------------------
#define BK 32
#define NKB2 32
#define STAGES 3
#define ABUF 8192
#define BBUF 8192
#define STG_BYTES (2 * ABUF + 2 * BBUF)

template<int MODE, int NN>
__global__ __launch_bounds__(256)
void tc_gemm(const unsigned short* __restrict__ Ah, const unsigned short* __restrict__ Al,
             const unsigned short* __restrict__ Bh, const unsigned short* __restrict__ Bl,
             float* __restrict__ Cout)
{
    extern __shared__ __align__(1024) unsigned char gsm[];
    const uint32_t sbase = s2u(gsm);
    const int tid = threadIdx.x;
    const int lane = tid & 31, wid = tid >> 5;
    const int wm = wid & 3, wn = wid >> 2;
    const int bm = blockIdx.y * 128, bn = blockIdx.x * 128;

    const unsigned short* Abases[2] = { Ah + (size_t)bm * 1024, Al + (size_t)bm * 1024 };
    const unsigned short* Bbases[2] = { Bh + bn, Bl + bn };

    auto load_stage = [&](int st, int kb) {
        uint32_t sb = sbase + st * STG_BYTES;
#pragma unroll
        for (int sp = 0; sp < 2; sp++) {
#pragma unroll
            for (int i = 0; i < 2; i++) {
                int id = i * 256 + tid;
                int r = id >> 2, c = id & 3;
                cpa16(sb + sp * ABUF + SWA(r * 64 + c * 16),
                      Abases[sp] + (size_t)r * 1024 + kb * BK + c * 8);
                int rk = id >> 4, cc = id & 15;
                cpa16(sb + 2 * ABUF + sp * BBUF + SWB(rk * 256 + cc * 16),
                      Bbases[sp] + (size_t)(kb * BK + rk) * NN + cc * 8);
            }
        }
    };

    float acc[2][8][4];
#pragma unroll
    for (int mt = 0; mt < 2; mt++)
#pragma unroll
        for (int nt = 0; nt < 8; nt++)
#pragma unroll
            for (int q = 0; q < 4; q++) acc[mt][nt][q] = 0.f;

    load_stage(0, 0); cpa_commit();
    load_stage(1, 1); cpa_commit();

    const int a_lr = lane & 15;
    const int a_hk = (lane >> 4) << 4;

    for (int kb = 0; kb < NKB2; kb++) {
        const int cur = kb % STAGES;
        if (kb >= NKB2 - 2) cpa_wait<0>(); else cpa_wait<1>();
        __syncthreads();
        // stage (kb+2)%3 was last read at iter kb-1; the barrier above seals it.
        if (kb + STAGES - 1 < NKB2) {
            load_stage((kb + STAGES - 1) % STAGES, kb + STAGES - 1);
            cpa_commit();
        }

        uint32_t sb = sbase + cur * STG_BYTES;
#pragma unroll
        for (int ks = 0; ks < 2; ks++) {
            uint32_t afr[2][2][4];
#pragma unroll
            for (int sp = 0; sp < 2; sp++)
#pragma unroll
                for (int mt = 0; mt < 2; mt++) {
                    int r = wm * 32 + mt * 16 + a_lr;
                    ldsm4(afr[sp][mt], sb + sp * ABUF + SWA(r * 64 + ks * 32 + a_hk));
                }
            uint32_t bfr[2][8][2];
#pragma unroll
            for (int sp = 0; sp < 2; sp++)
#pragma unroll
                for (int nt2 = 0; nt2 < 4; nt2++) {
                    int kk = ks * 16 + a_lr;
                    int nb = wn * 128 + nt2 * 32 + a_hk;
                    uint32_t t[4];
                    ldsm4t(t, sb + 2 * ABUF + sp * BBUF + SWB(kk * 256 + nb));
                    bfr[sp][nt2 * 2][0] = t[0]; bfr[sp][nt2 * 2][1] = t[1];
                    bfr[sp][nt2 * 2 + 1][0] = t[2]; bfr[sp][nt2 * 2 + 1][1] = t[3];
                }
#pragma unroll
            for (int mt = 0; mt < 2; mt++)
#pragma unroll
                for (int nt = 0; nt < 8; nt++) {
                    mma16816(acc[mt][nt], afr[0][mt], bfr[0][nt]);
                    mma16816(acc[mt][nt], afr[0][mt], bfr[1][nt]);
                    mma16816(acc[mt][nt], afr[1][mt], bfr[0][nt]);
                }
        }
    }

    const int gid = lane >> 2, tg = lane & 3;
#pragma unroll
    for (int mt = 0; mt < 2; mt++)
#pragma unroll
        for (int nt = 0; nt < 8; nt++) {
            int row0 = bm + wm * 32 + mt * 16 + gid;
            int col = bn + wn * 64 + nt * 8 + tg * 2;
#pragma unroll
            for (int half = 0; half < 2; half++) {
                int row = row0 + half * 8;
                float v0 = acc[mt][nt][half * 2], v1 = acc[mt][nt][half * 2 + 1];
                if (MODE == 0) {
                    int s = col >> 10, h = (col >> 6) & 15, d = col & 63;
                    int b = row >> 11, t = row & 2047;
                    size_t idx = (size_t)s * QKV_STRIDE +
                                 (((size_t)(b * Hn + h) * Tn + t) << 6) + d;
                    unsigned short h0, l0, h1, l1;
                    split1(v0, h0, l0);
                    split1(v1, h1, l1);
                    *(uint32_t*)&qkvh[idx] = (uint32_t)h0 | ((uint32_t)h1 << 16);
                    *(uint32_t*)&qkvl[idx] = (uint32_t)l0 | ((uint32_t)l1 << 16);
                } else {
                    *(float2*)&Cout[(size_t)row * NN + col] = make_float2(v0, v1);
                }
            }
        }
}

// ---------------------------------------------------------------------------
// Tensor-core flash attention (bf16x3 QK^T and PV, fp32 accum).
// 256 threads = 8 warps; block = 128 q rows of one (b,h); warp owns 16 rows.
// One __syncthreads per kv-iteration.
// ---------------------------------------------------------------------------
#define AQ_OFF 0                     // Q hi 16KB (128 rows x 128B)
#define AQL_OFF 16384                // Q lo 16KB
#define AKV_OFF 32768                // 2 stages x (Kh,Kl,Vh,Vl) 8KB each = 64KB
#define APOS_OFF (32768 + 65536)     // 98304
#define ATTN_SMEM_SZ (32768 + 65536 + 512)

__global__ __launch_bounds__(256)
void attn_mma(const int* __restrict__ pos)
{
    extern __shared__ __align__(1024) unsigned char am[];
    const uint32_t sb = s2u(am);
    const int tid = threadIdx.x, lane = tid & 31, wm = tid >> 5;   // wm 0..7
    const int b = blockIdx.y >> 4, h = blockIdx.y & 15;
    const int i0 = blockIdx.x * 128;

    const size_t bh_off = ((size_t)(b * Hn + h) * Tn) << 6;
    const unsigned short* Qhg = qkvh + bh_off + ((size_t)i0 << 6);
    const unsigned short* Qlg = qkvl + bh_off + ((size_t)i0 << 6);
    const unsigned short* Khg = qkvh + (size_t)QKV_STRIDE + bh_off;
    const unsigned short* Klg = qkvl + (size_t)QKV_STRIDE + bh_off;
    const unsigned short* Vhg = qkvh + 2ull * QKV_STRIDE + bh_off;
    const unsigned short* Vlg = qkvl + 2ull * QKV_STRIDE + bh_off;
    const int* posb = pos + b * Tn;

    // Q tile (128 rows, hi+lo) -> smem
#pragma unroll
    for (int i = 0; i < 4; i++) {
        int id = tid + i * 256;            // 0..1023
        int r = id >> 3, c = id & 7;
        cpa16(sb + AQ_OFF + SW128(r * 128 + c * 16), Qhg + (size_t)r * 64 + c * 8);
        cpa16(sb + AQL_OFF + SW128(r * 128 + c * 16), Qlg + (size_t)r * 64 + c * 8);
    }
    cpa_commit();

    auto load_kv = [&](int st, int j0) {
        uint32_t base = sb + AKV_OFF + st * 32768;
        const unsigned short* srcs[4] = {
            Khg + ((size_t)j0 << 6), Klg + ((size_t)j0 << 6),
            Vhg + ((size_t)j0 << 6), Vlg + ((size_t)j0 << 6) };
#pragma unroll
        for (int buf = 0; buf < 4; buf++)
#pragma unroll
            for (int i = 0; i < 2; i++) {
                int id = tid + i * 256;      // 0..511
                int r = id >> 3, c = id & 7;
                cpa16(base + buf * 8192 + SW128(r * 128 + c * 16),
                      srcs[buf] + (size_t)r * 64 + c * 8);
            }
        if (tid < 16)
            cpa16(sb + APOS_OFF + st * 256 + tid * 16, posb + j0 + tid * 4);
    };

    load_kv(0, 0);
    cpa_commit();

    // Q ready (stage-0 group may stay pending)
    cpa_wait<1>();
    __syncthreads();
    const int a_lr = lane & 15, a_hk = (lane >> 4) << 4;
    uint32_t qfh[4][4], qfl[4][4];
#pragma unroll
    for (int ks = 0; ks < 4; ks++) {
        int r = wm * 16 + a_lr;
        ldsm4(qfh[ks], sb + AQ_OFF + SW128(r * 128 + ks * 32 + a_hk));
        ldsm4(qfl[ks], sb + AQL_OFF + SW128(r * 128 + ks * 32 + a_hk));
    }

    const int pq0 = posb[i0 + wm * 16 + (lane >> 2)];
    const int pq1 = posb[i0 + wm * 16 + (lane >> 2) + 8];
    const int pqmax = posb[i0 + 127];
    const int jcol = 2 * (lane & 3);

    float m0 = -3e38f, m1 = -3e38f, l0 = 0.f, l1 = 0.f;
    float oacc[8][4];
#pragma unroll
    for (int nt = 0; nt < 8; nt++)
#pragma unroll
        for (int q = 0; q < 4; q++) oacc[nt][q] = 0.f;

    const float CS = 0.18033688011112042f;   // 0.125 * log2(e)

    int jb = 0, st = 0;
    for (;;) {
        int next = jb + 64;
        bool hn = (next < Tn) && (posb[next] <= pqmax);

        cpa_wait<0>();          // current stage fully resident
        __syncthreads();        // also seals last iter's reads of stage st^1
        if (hn) { load_kv(st ^ 1, next); cpa_commit(); }

        const uint32_t kb_ = sb + AKV_OFF + st * 32768;
        const int* pkp = (const int*)(am + APOS_OFF + st * 256);

        float sacc[8][4];
#pragma unroll
        for (int nt = 0; nt < 8; nt++)
#pragma unroll
            for (int q = 0; q < 4; q++) sacc[nt][q] = 0.f;

#pragma unroll
        for (int ks = 0; ks < 4; ks++) {
            uint32_t kfh[4][4], kfl[4][4];
            const int g = lane >> 3;
            const int krow = (g >> 1) * 8 + (lane & 7);
            const int kchk = ks * 32 + (g & 1) * 16;
#pragma unroll
            for (int call = 0; call < 4; call++) {
                uint32_t off = SW128((call * 16 + krow) * 128 + kchk);
                ldsm4(kfh[call], kb_ + off);
                ldsm4(kfl[call], kb_ + 8192 + off);
            }
#pragma unroll
            for (int nt = 0; nt < 8; nt++) {
                const int c = nt >> 1, hf = (nt & 1) * 2;
                mma16816(sacc[nt], qfh[ks], &kfh[c][hf]);
                mma16816(sacc[nt], qfh[ks], &kfl[c][hf]);
                mma16816(sacc[nt], qfl[ks], &kfh[c][hf]);
            }
        }

        float mx0 = m0, mx1 = m1;
#pragma unroll
        for (int nt = 0; nt < 8; nt++) {
            int pk0 = pkp[nt * 8 + jcol], pk1 = pkp[nt * 8 + jcol + 1];
            float v0 = (pq0 < pk0) ? -3e38f : sacc[nt][0] * CS;
            float v1 = (pq0 < pk1) ? -3e38f : sacc[nt][1] * CS;
            float v2 = (pq1 < pk0) ? -3e38f : sacc[nt][2] * CS;
            float v3 = (pq1 < pk1) ? -3e38f : sacc[nt][3] * CS;
            sacc[nt][0] = v0; sacc[nt][1] = v1;
            sacc[nt][2] = v2; sacc[nt][3] = v3;
            mx0 = fmaxf(mx0, fmaxf(v0, v1));
            mx1 = fmaxf(mx1, fmaxf(v2, v3));
        }
        mx0 = fmaxf(mx0, __shfl_xor_sync(0xffffffffu, mx0, 1));
        mx0 = fmaxf(mx0, __shfl_xor_sync(0xffffffffu, mx0, 2));
        mx1 = fmaxf(mx1, __shfl_xor_sync(0xffffffffu, mx1, 1));
        mx1 = fmaxf(mx1, __shfl_xor_sync(0xffffffffu, mx1, 2));
        float al0 = exp2f(m0 - mx0), al1 = exp2f(m1 - mx1);
        m0 = mx0; m1 = mx1;

        float s0 = 0.f, s1 = 0.f;
#pragma unroll
        for (int nt = 0; nt < 8; nt++) {
            float p0 = exp2f(sacc[nt][0] - mx0);
            float p1 = exp2f(sacc[nt][1] - mx0);
            float p2 = exp2f(sacc[nt][2] - mx1);
            float p3 = exp2f(sacc[nt][3] - mx1);
            sacc[nt][0] = p0; sacc[nt][1] = p1;
            sacc[nt][2] = p2; sacc[nt][3] = p3;
            s0 += p0 + p1; s1 += p2 + p3;
        }
        s0 += __shfl_xor_sync(0xffffffffu, s0, 1);
        s0 += __shfl_xor_sync(0xffffffffu, s0, 2);
        s1 += __shfl_xor_sync(0xffffffffu, s1, 1);
        s1 += __shfl_xor_sync(0xffffffffu, s1, 2);
        l0 = l0 * al0 + s0;
        l1 = l1 * al1 + s1;
#pragma unroll
        for (int nt = 0; nt < 8; nt++) {
            oacc[nt][0] *= al0; oacc[nt][1] *= al0;
            oacc[nt][2] *= al1; oacc[nt][3] *= al1;
        }

        const uint32_t vb = kb_ + 16384;
#pragma unroll
        for (int kt = 0; kt < 4; kt++) {
            uint32_t ph[4], pl[4];
#pragma unroll
            for (int q = 0; q < 4; q++) {
                const float* src = (q < 2) ? sacc[2 * kt] : sacc[2 * kt + 1];
                float a = src[(q & 1) * 2], c = src[(q & 1) * 2 + 1];
                uint32_t hp = pack_bf2(a, c);
                ph[q] = hp;
                float hl = __uint_as_float(hp << 16);
                float hh = __uint_as_float(hp & 0xFFFF0000u);
                pl[q] = pack_bf2(a - hl, c - hh);
            }
            uint32_t vfh[4][4], vfl[4][4];
#pragma unroll
            for (int call = 0; call < 4; call++) {
                uint32_t off = SW128((kt * 16 + a_lr) * 128 + call * 32 + a_hk);
                ldsm4t(vfh[call], vb + off);
                ldsm4t(vfl[call], vb + 8192 + off);
            }
#pragma unroll
            for (int nt = 0; nt < 8; nt++) {
                const int c = nt >> 1, hf = (nt & 1) * 2;
                mma16816(oacc[nt], ph, &vfh[c][hf]);
                mma16816(oacc[nt], ph, &vfl[c][hf]);
                mma16816(oacc[nt], pl, &vfh[c][hf]);
            }
        }

        if (!hn) break;
        jb = next; st ^= 1;
    }

    float inv0 = 1.f / l0, inv1 = 1.f / l1;
    int t0r = i0 + wm * 16 + (lane >> 2);
#pragma unroll
    for (int nt = 0; nt < 8; nt++) {
        int col = h * 64 + nt * 8 + jcol;
#pragma unroll
        for (int half = 0; half < 2; half++) {
            int t = t0r + half * 8;
            float inv = half ? inv1 : inv0;
            float v0 = oacc[nt][half * 2] * inv;
            float v1 = oacc[nt][half * 2 + 1] * inv;
            unsigned short h0, lw0, h1, lw1;
            split1(v0, h0, lw0);
            split1(v1, h1, lw1);
            size_t idx = ((size_t)b * Tn + t) * Dn + col;
            *(uint32_t*)&ga_hi[idx] = (uint32_t)h0 | ((uint32_t)h1 << 16);
            *(uint32_t*)&ga_lo[idx] = (uint32_t)lw0 | ((uint32_t)lw1 << 16);
        }
    }
}

// ---------------------------------------------------------------------------
extern "C" void kernel_launch(void* const* d_in, const int* in_sizes, int n_in,
                              void* d_out, int out_size)
{
    const float* x   = (const float*)d_in[0];
    const int*   pos = (const int*)d_in[1];
    const float* Wq  = (const float*)d_in[2];
    const float* Wo  = (const float*)d_in[3];
    float* out = (float*)d_out;

    unsigned short *p_xh, *p_xl, *p_wqh, *p_wql, *p_woh, *p_wol, *p_gah, *p_gal;
    cudaGetSymbolAddress((void**)&p_xh,  xa_hi);
    cudaGetSymbolAddress((void**)&p_xl,  xa_lo);
    cudaGetSymbolAddress((void**)&p_wqh, wq_hi);
    cudaGetSymbolAddress((void**)&p_wql, wq_lo);
    cudaGetSymbolAddress((void**)&p_woh, wo_hi);
    cudaGetSymbolAddress((void**)&p_wol, wo_lo);
    cudaGetSymbolAddress((void**)&p_gah, ga_hi);
    cudaGetSymbolAddress((void**)&p_gal, ga_lo);

    const int GEMM_SMEM = STAGES * STG_BYTES;   // 98304

    // 0) bf16 hi/lo splits
    int n4x = (Bn * Tn * Dn) / 4;
    split_kernel<<<(n4x + 255) / 256, 256>>>(x, p_xh, p_xl, n4x);
    int n4wq = (3 * Dn * Dn) / 4;
    split_kernel<<<(n4wq + 255) / 256, 256>>>(Wq, p_wqh, p_wql, n4wq);
    int n4wo = (Dn * Dn) / 4;
    split_kernel<<<(n4wo + 255) / 256, 256>>>(Wo, p_woh, p_wol, n4wo);

    // 1) QKV projection -> qkvh/qkvl (bf16 hi/lo, scattered)
    cudaFuncSetAttribute(tc_gemm<0, 3072>,
                         cudaFuncAttributeMaxDynamicSharedMemorySize, GEMM_SMEM);
    tc_gemm<0, 3072><<<dim3(24, 64), 256, GEMM_SMEM>>>(p_xh, p_xl, p_wqh, p_wql, nullptr);

    // 2) tensor-core flash attention (128 q-rows / block) -> ga_hi/ga_lo
    cudaFuncSetAttribute(attn_mma,
                         cudaFuncAttributeMaxDynamicSharedMemorySize, ATTN_SMEM_SZ);
    attn_mma<<<dim3(Tn / 128, Bn * Hn), 256, ATTN_SMEM_SZ>>>(pos);

    // 3) output projection -> d_out
    cudaFuncSetAttribute(tc_gemm<1, 1024>,
                         cudaFuncAttributeMaxDynamicSharedMemorySize, GEMM_SMEM);
    tc_gemm<1, 1024><<<dim3(8, 64), 256, GEMM_SMEM>>>(p_gah, p_gal, p_woh, p_wol, out);
}

// round 7
// speedup vs baseline: 1.3200x; 1.2160x over previous
#include <cuda_runtime.h>
#include <cuda_fp16.h>
#include <math.h>
#include <stdint.h>

// Problem constants
#define Bn 4
#define Tn 2048
#define Dn 1024
#define Hn 16
#define HDn 64
#define QKV_STRIDE (Bn * Hn * Tn * HDn)   // 8388608 elems per q/k/v

// ---------------------------------------------------------------------------
// Device scratch (no cudaMalloc allowed).  All u16 = fp16 bits.
// ---------------------------------------------------------------------------
__device__ unsigned short qkvh[3ull * QKV_STRIDE];      // [3][B][H][T][HD] fp16 hi (k,v: single)
__device__ unsigned short qkvl[3ull * QKV_STRIDE];      // fp16 lo (only q section used)
__device__ unsigned short xa_hi[(size_t)Bn * Tn * Dn];  // x split [8192][1024]
__device__ unsigned short xa_lo[(size_t)Bn * Tn * Dn];
__device__ unsigned short wq_h[(size_t)3 * Dn * Dn];    // Wqkv fp16 (native K-major)
__device__ unsigned short wo_h[(size_t)Dn * Dn];        // Wout fp16
__device__ unsigned short ga_hi[(size_t)Bn * Tn * Dn];  // attention out split
__device__ unsigned short ga_lo[(size_t)Bn * Tn * Dn];

// ---------------------------------------------------------------------------
// PTX helpers (non-arch-suffixed; valid on plain sm_103 target)
// ---------------------------------------------------------------------------
__device__ __forceinline__ uint32_t s2u(const void* p) {
    uint32_t a;
    asm("{ .reg .u64 t; cvta.to.shared.u64 t, %1; cvt.u32.u64 %0, t; }"
        : "=r"(a) : "l"(p));
    return a;
}
__device__ __forceinline__ void cpa16(uint32_t d, const void* s) {
    asm volatile("cp.async.cg.shared.global [%0], [%1], 16;"
                 :: "r"(d), "l"(s) : "memory");
}
__device__ __forceinline__ void cpa_commit() {
    asm volatile("cp.async.commit_group;" ::: "memory");
}
template<int N>
__device__ __forceinline__ void cpa_wait() {
    asm volatile("cp.async.wait_group %0;" :: "n"(N) : "memory");
}
__device__ __forceinline__ void ldsm4(uint32_t* r, uint32_t a) {
    asm volatile("ldmatrix.sync.aligned.m8n8.x4.shared.b16 {%0,%1,%2,%3}, [%4];"
        : "=r"(r[0]), "=r"(r[1]), "=r"(r[2]), "=r"(r[3]) : "r"(a));
}
__device__ __forceinline__ void ldsm4t(uint32_t* r, uint32_t a) {
    asm volatile("ldmatrix.sync.aligned.m8n8.x4.trans.shared.b16 {%0,%1,%2,%3}, [%4];"
        : "=r"(r[0]), "=r"(r[1]), "=r"(r[2]), "=r"(r[3]) : "r"(a));
}
__device__ __forceinline__ void mma16816(float* d, const uint32_t* a, const uint32_t* b) {
    asm volatile(
        "mma.sync.aligned.m16n8k16.row.col.f32.f16.f16.f32 "
        "{%0,%1,%2,%3}, {%4,%5,%6,%7}, {%8,%9}, {%0,%1,%2,%3};"
        : "+f"(d[0]), "+f"(d[1]), "+f"(d[2]), "+f"(d[3])
        : "r"(a[0]), "r"(a[1]), "r"(a[2]), "r"(a[3]), "r"(b[0]), "r"(b[1]));
}
// pack two f32 into f16x2: low half <- a, high half <- c
__device__ __forceinline__ uint32_t pack_hf2(float a, float c) {
    uint32_t d;
    asm("cvt.rn.f16x2.f32 %0, %1, %2;" : "=r"(d) : "f"(c), "f"(a));
    return d;
}

// Swizzles
#define SWA(o) ((o) ^ ((((o) >> 7) & 3) << 4))   // 64B rows (GEMM A/B bufs)
#define SWB(o) ((o) ^ ((((o) >> 8) & 7) << 4))   // 256B rows (GEMM B buf)
#define SW128(o) ((o) ^ ((((o) >> 7) & 7) << 4)) // 128B rows (attention)

// ---------------------------------------------------------------------------
// fp32 -> (fp16 hi, fp16 lo)
// ---------------------------------------------------------------------------
__device__ __forceinline__ void split1(float v, unsigned short& h, unsigned short& l) {
    __half hb = __float2half_rn(v);
    float r = v - __half2float(hb);
    __half lb = __float2half_rn(r);
    h = reinterpret_cast<unsigned short&>(hb);
    l = reinterpret_cast<unsigned short&>(lb);
}

__global__ __launch_bounds__(256)
void split_kernel(const float* __restrict__ in, unsigned short* __restrict__ hi,
                  unsigned short* __restrict__ lo, int n4)
{
    int i = blockIdx.x * 256 + threadIdx.x;
    if (i >= n4) return;
    float4 v = ((const float4*)in)[i];
    ushort4 h, l;
    split1(v.x, h.x, l.x);
    split1(v.y, h.y, l.y);
    split1(v.z, h.z, l.z);
    split1(v.w, h.w, l.w);
    ((ushort4*)hi)[i] = h;
    ((ushort4*)lo)[i] = l;
}

// fp32 -> single fp16 (weights)
__global__ __launch_bounds__(256)
void conv_kernel(const float* __restrict__ in, unsigned short* __restrict__ hi, int n4)
{
    int i = blockIdx.x * 256 + threadIdx.x;
    if (i >= n4) return;
    float4 v = ((const float4*)in)[i];
    __half a = __float2half_rn(v.x), b = __float2half_rn(v.y);
    __half c = __float2half_rn(v.z), d = __float2half_rn(v.w);
    ushort4 h;
    h.x = reinterpret_cast<unsigned short&>(a);
    h.y = reinterpret_cast<unsigned short&>(b);
    h.z = reinterpret_cast<unsigned short&>(c);
    h.w = reinterpret_cast<unsigned short&>(d);
    ((ushort4*)hi)[i] = h;
}

// ---------------------------------------------------------------------------
// fp16x2 GEMM via mma.sync: D[8192][NN] = (Ah+Al)[8192][1024] @ Bh[1024][NN]
// 128x128 CTA tile, BK=32, 4-stage cp.async pipeline, 8 warps (4m x 2n),
// warp tile 32x64.  One sync per k-block.
// MODE 0: scatter into qkvh (+qkvl for q).  MODE 1: fp32 write to Cout.
// ---------------------------------------------------------------------------
#define BK 32
#define NKB2 32
#define STAGES 4
#define ABUF 8192                     // 128 x 32 fp16
#define BBUF 8192                     // 32 x 128 fp16
#define STG_BYTES (2 * ABUF + BBUF)   // 24576

template<int MODE, int NN>
__global__ __launch_bounds__(256)
void tc_gemm(const unsigned short* __restrict__ Ah, const unsigned short* __restrict__ Al,
             const unsigned short* __restrict__ Bh, float* __restrict__ Cout)
{
    extern __shared__ __align__(1024) unsigned char gsm[];
    const uint32_t sbase = s2u(gsm);
    const int tid = threadIdx.x;
    const int lane = tid & 31, wid = tid >> 5;
    const int wm = wid & 3, wn = wid >> 2;
    const int bm = blockIdx.y * 128, bn = blockIdx.x * 128;

    const unsigned short* Abases[2] = { Ah + (size_t)bm * 1024, Al + (size_t)bm * 1024 };
    const unsigned short* Bbase = Bh + bn;

    auto load_stage = [&](int st, int kb) {
        uint32_t sb = sbase + st * STG_BYTES;
#pragma unroll
        for (int sp = 0; sp < 2; sp++) {
#pragma unroll
            for (int i = 0; i < 2; i++) {
                int id = i * 256 + tid;          // 0..511
                int r = id >> 2, c = id & 3;
                cpa16(sb + sp * ABUF + SWA(r * 64 + c * 16),
                      Abases[sp] + (size_t)r * 1024 + kb * BK + c * 8);
            }
        }
#pragma unroll
        for (int i = 0; i < 2; i++) {
            int id = i * 256 + tid;
            int rk = id >> 4, cc = id & 15;
            cpa16(sb + 2 * ABUF + SWB(rk * 256 + cc * 16),
                  Bbase + (size_t)(kb * BK + rk) * NN + cc * 8);
        }
    };

    float acc[2][8][4];
#pragma unroll
    for (int mt = 0; mt < 2; mt++)
#pragma unroll
        for (int nt = 0; nt < 8; nt++)
#pragma unroll
            for (int q = 0; q < 4; q++) acc[mt][nt][q] = 0.f;

    load_stage(0, 0); cpa_commit();
    load_stage(1, 1); cpa_commit();
    load_stage(2, 2); cpa_commit();

    const int a_lr = lane & 15;
    const int a_hk = (lane >> 4) << 4;

    for (int kb = 0; kb < NKB2; kb++) {
        const int cur = kb & 3;
        if (kb < NKB2 - 2) cpa_wait<2>();
        else if (kb == NKB2 - 2) cpa_wait<1>();
        else cpa_wait<0>();
        __syncthreads();
        // stage (kb+3)&3 was last read at iter kb-1; the barrier above seals it.
        if (kb + 3 < NKB2) { load_stage((kb + 3) & 3, kb + 3); cpa_commit(); }

        uint32_t sb = sbase + cur * STG_BYTES;
#pragma unroll
        for (int ks = 0; ks < 2; ks++) {
            uint32_t afr[2][2][4];
#pragma unroll
            for (int sp = 0; sp < 2; sp++)
#pragma unroll
                for (int mt = 0; mt < 2; mt++) {
                    int r = wm * 32 + mt * 16 + a_lr;
                    ldsm4(afr[sp][mt], sb + sp * ABUF + SWA(r * 64 + ks * 32 + a_hk));
                }
            uint32_t bfr[8][2];
#pragma unroll
            for (int nt2 = 0; nt2 < 4; nt2++) {
                int kk = ks * 16 + a_lr;
                int nb = wn * 128 + nt2 * 32 + a_hk;
                uint32_t t[4];
                ldsm4t(t, sb + 2 * ABUF + SWB(kk * 256 + nb));
                bfr[nt2 * 2][0] = t[0]; bfr[nt2 * 2][1] = t[1];
                bfr[nt2 * 2 + 1][0] = t[2]; bfr[nt2 * 2 + 1][1] = t[3];
            }
#pragma unroll
            for (int mt = 0; mt < 2; mt++)
#pragma unroll
                for (int nt = 0; nt < 8; nt++) {
                    mma16816(acc[mt][nt], afr[0][mt], bfr[nt]);
                    mma16816(acc[mt][nt], afr[1][mt], bfr[nt]);
                }
        }
    }

    const int gid = lane >> 2, tg = lane & 3;
#pragma unroll
    for (int mt = 0; mt < 2; mt++)
#pragma unroll
        for (int nt = 0; nt < 8; nt++) {
            int row0 = bm + wm * 32 + mt * 16 + gid;
            int col = bn + wn * 64 + nt * 8 + tg * 2;
#pragma unroll
            for (int half = 0; half < 2; half++) {
                int row = row0 + half * 8;
                float v0 = acc[mt][nt][half * 2], v1 = acc[mt][nt][half * 2 + 1];
                if (MODE == 0) {
                    int s = col >> 10, h = (col >> 6) & 15, d = col & 63;
                    int b = row >> 11, t = row & 2047;
                    size_t idx = (size_t)s * QKV_STRIDE +
                                 (((size_t)(b * Hn + h) * Tn + t) << 6) + d;
                    unsigned short h0, l0, h1, l1;
                    split1(v0, h0, l0);
                    split1(v1, h1, l1);
                    *(uint32_t*)&qkvh[idx] = (uint32_t)h0 | ((uint32_t)h1 << 16);
                    if (s == 0)
                        *(uint32_t*)&qkvl[idx] = (uint32_t)l0 | ((uint32_t)l1 << 16);
                } else {
                    *(float2*)&Cout[(size_t)row * NN + col] = make_float2(v0, v1);
                }
            }
        }
}

// ---------------------------------------------------------------------------
// Tensor-core flash attention, fp16x2 scheme.
// Q split hi/lo (exact); K,V single fp16.  256 threads = 8 warps; 128 q rows.
// ---------------------------------------------------------------------------
#define AQ_OFF 0                     // Q hi 16KB (128 rows x 128B)
#define AQL_OFF 16384                // Q lo 16KB
#define AKV_OFF 32768                // 2 stages x (K 8KB + V 8KB)
#define APOS_OFF (32768 + 32768)     // 65536
#define ATTN_SMEM_SZ (32768 + 32768 + 512)

__global__ __launch_bounds__(256)
void attn_mma(const int* __restrict__ pos)
{
    extern __shared__ __align__(1024) unsigned char am[];
    const uint32_t sb = s2u(am);
    const int tid = threadIdx.x, lane = tid & 31, wm = tid >> 5;   // wm 0..7
    const int b = blockIdx.y >> 4, h = blockIdx.y & 15;
    const int i0 = blockIdx.x * 128;

    const size_t bh_off = ((size_t)(b * Hn + h) * Tn) << 6;
    const unsigned short* Qhg = qkvh + bh_off + ((size_t)i0 << 6);
    const unsigned short* Qlg = qkvl + bh_off + ((size_t)i0 << 6);
    const unsigned short* Khg = qkvh + (size_t)QKV_STRIDE + bh_off;
    const unsigned short* Vhg = qkvh + 2ull * QKV_STRIDE + bh_off;
    const int* posb = pos + b * Tn;

    // Q tile (128 rows, hi+lo) -> smem
#pragma unroll
    for (int i = 0; i < 4; i++) {
        int id = tid + i * 256;            // 0..1023
        int r = id >> 3, c = id & 7;
        cpa16(sb + AQ_OFF + SW128(r * 128 + c * 16), Qhg + (size_t)r * 64 + c * 8);
        cpa16(sb + AQL_OFF + SW128(r * 128 + c * 16), Qlg + (size_t)r * 64 + c * 8);
    }
    cpa_commit();

    auto load_kv = [&](int st, int j0) {
        uint32_t base = sb + AKV_OFF + st * 16384;
        const unsigned short* srcs[2] = {
            Khg + ((size_t)j0 << 6), Vhg + ((size_t)j0 << 6) };
#pragma unroll
        for (int buf = 0; buf < 2; buf++)
#pragma unroll
            for (int i = 0; i < 2; i++) {
                int id = tid + i * 256;      // 0..511
                int r = id >> 3, c = id & 7;
                cpa16(base + buf * 8192 + SW128(r * 128 + c * 16),
                      srcs[buf] + (size_t)r * 64 + c * 8);
            }
        if (tid < 16)
            cpa16(sb + APOS_OFF + st * 256 + tid * 16, posb + j0 + tid * 4);
    };

    load_kv(0, 0);
    cpa_commit();

    cpa_wait<1>();
    __syncthreads();
    const int a_lr = lane & 15, a_hk = (lane >> 4) << 4;
    uint32_t qfh[4][4], qfl[4][4];
#pragma unroll
    for (int ks = 0; ks < 4; ks++) {
        int r = wm * 16 + a_lr;
        ldsm4(qfh[ks], sb + AQ_OFF + SW128(r * 128 + ks * 32 + a_hk));
        ldsm4(qfl[ks], sb + AQL_OFF + SW128(r * 128 + ks * 32 + a_hk));
    }

    const int pq0 = posb[i0 + wm * 16 + (lane >> 2)];
    const int pq1 = posb[i0 + wm * 16 + (lane >> 2) + 8];
    const int pqmax = posb[i0 + 127];
    const int jcol = 2 * (lane & 3);

    float m0 = -3e38f, m1 = -3e38f, l0 = 0.f, l1 = 0.f;
    float oacc[8][4];
#pragma unroll
    for (int nt = 0; nt < 8; nt++)
#pragma unroll
        for (int q = 0; q < 4; q++) oacc[nt][q] = 0.f;

    const float CS = 0.18033688011112042f;   // 0.125 * log2(e)

    int jb = 0, st = 0;
    for (;;) {
        int next = jb + 64;
        bool hn = (next < Tn) && (posb[next] <= pqmax);

        cpa_wait<0>();          // current stage fully resident
        __syncthreads();        // seals last iter's reads of stage st^1
        if (hn) { load_kv(st ^ 1, next); cpa_commit(); }

        const uint32_t kb_ = sb + AKV_OFF + st * 16384;
        const int* pkp = (const int*)(am + APOS_OFF + st * 256);

        float sacc[8][4];
#pragma unroll
        for (int nt = 0; nt < 8; nt++)
#pragma unroll
            for (int q = 0; q < 4; q++) sacc[nt][q] = 0.f;

#pragma unroll
        for (int ks = 0; ks < 4; ks++) {
            uint32_t kf[4][4];
            const int g = lane >> 3;
            const int krow = (g >> 1) * 8 + (lane & 7);
            const int kchk = ks * 32 + (g & 1) * 16;
#pragma unroll
            for (int call = 0; call < 4; call++) {
                uint32_t off = SW128((call * 16 + krow) * 128 + kchk);
                ldsm4(kf[call], kb_ + off);
            }
#pragma unroll
            for (int nt = 0; nt < 8; nt++) {
                const int c = nt >> 1, hf = (nt & 1) * 2;
                mma16816(sacc[nt], qfh[ks], &kf[c][hf]);
                mma16816(sacc[nt], qfl[ks], &kf[c][hf]);
            }
        }

        float mx0 = m0, mx1 = m1;
#pragma unroll
        for (int nt = 0; nt < 8; nt++) {
            int pk0 = pkp[nt * 8 + jcol], pk1 = pkp[nt * 8 + jcol + 1];
            float v0 = (pq0 < pk0) ? -3e38f : sacc[nt][0] * CS;
            float v1 = (pq0 < pk1) ? -3e38f : sacc[nt][1] * CS;
            float v2 = (pq1 < pk0) ? -3e38f : sacc[nt][2] * CS;
            float v3 = (pq1 < pk1) ? -3e38f : sacc[nt][3] * CS;
            sacc[nt][0] = v0; sacc[nt][1] = v1;
            sacc[nt][2] = v2; sacc[nt][3] = v3;
            mx0 = fmaxf(mx0, fmaxf(v0, v1));
            mx1 = fmaxf(mx1, fmaxf(v2, v3));
        }
        mx0 = fmaxf(mx0, __shfl_xor_sync(0xffffffffu, mx0, 1));
        mx0 = fmaxf(mx0, __shfl_xor_sync(0xffffffffu, mx0, 2));
        mx1 = fmaxf(mx1, __shfl_xor_sync(0xffffffffu, mx1, 1));
        mx1 = fmaxf(mx1, __shfl_xor_sync(0xffffffffu, mx1, 2));
        float al0 = exp2f(m0 - mx0), al1 = exp2f(m1 - mx1);
        m0 = mx0; m1 = mx1;

        float s0 = 0.f, s1 = 0.f;
#pragma unroll
        for (int nt = 0; nt < 8; nt++) {
            float p0 = exp2f(sacc[nt][0] - mx0);
            float p1 = exp2f(sacc[nt][1] - mx0);
            float p2 = exp2f(sacc[nt][2] - mx1);
            float p3 = exp2f(sacc[nt][3] - mx1);
            sacc[nt][0] = p0; sacc[nt][1] = p1;
            sacc[nt][2] = p2; sacc[nt][3] = p3;
            s0 += p0 + p1; s1 += p2 + p3;
        }
        s0 += __shfl_xor_sync(0xffffffffu, s0, 1);
        s0 += __shfl_xor_sync(0xffffffffu, s0, 2);
        s1 += __shfl_xor_sync(0xffffffffu, s1, 1);
        s1 += __shfl_xor_sync(0xffffffffu, s1, 2);
        l0 = l0 * al0 + s0;
        l1 = l1 * al1 + s1;
#pragma unroll
        for (int nt = 0; nt < 8; nt++) {
            oacc[nt][0] *= al0; oacc[nt][1] *= al0;
            oacc[nt][2] *= al1; oacc[nt][3] *= al1;
        }

        const uint32_t vb = kb_ + 8192;
#pragma unroll
        for (int kt = 0; kt < 4; kt++) {
            uint32_t ph[4], pl[4];
#pragma unroll
            for (int q = 0; q < 4; q++) {
                const float* src = (q < 2) ? sacc[2 * kt] : sacc[2 * kt + 1];
                float a = src[(q & 1) * 2], c = src[(q & 1) * 2 + 1];
                __half ha = __float2half_rn(a), hc = __float2half_rn(c);
                ph[q] = (uint32_t)reinterpret_cast<unsigned short&>(ha) |
                        ((uint32_t)reinterpret_cast<unsigned short&>(hc) << 16);
                pl[q] = pack_hf2(a - __half2float(ha), c - __half2float(hc));
            }
            uint32_t vf[4][4];
#pragma unroll
            for (int call = 0; call < 4; call++) {
                uint32_t off = SW128((kt * 16 + a_lr) * 128 + call * 32 + a_hk);
                ldsm4t(vf[call], vb + off);
            }
#pragma unroll
            for (int nt = 0; nt < 8; nt++) {
                const int c = nt >> 1, hf = (nt & 1) * 2;
                mma16816(oacc[nt], ph, &vf[c][hf]);
                mma16816(oacc[nt], pl, &vf[c][hf]);
            }
        }

        if (!hn) break;
        jb = next; st ^= 1;
    }

    float inv0 = 1.f / l0, inv1 = 1.f / l1;
    int t0r = i0 + wm * 16 + (lane >> 2);
#pragma unroll
    for (int nt = 0; nt < 8; nt++) {
        int col = h * 64 + nt * 8 + jcol;
#pragma unroll
        for (int half = 0; half < 2; half++) {
            int t = t0r + half * 8;
            float inv = half ? inv1 : inv0;
            float v0 = oacc[nt][half * 2] * inv;
            float v1 = oacc[nt][half * 2 + 1] * inv;
            unsigned short h0, lw0, h1, lw1;
            split1(v0, h0, lw0);
            split1(v1, h1, lw1);
            size_t idx = ((size_t)b * Tn + t) * Dn + col;
            *(uint32_t*)&ga_hi[idx] = (uint32_t)h0 | ((uint32_t)h1 << 16);
            *(uint32_t*)&ga_lo[idx] = (uint32_t)lw0 | ((uint32_t)lw1 << 16);
        }
    }
}

// ---------------------------------------------------------------------------
extern "C" void kernel_launch(void* const* d_in, const int* in_sizes, int n_in,
                              void* d_out, int out_size)
{
    const float* x   = (const float*)d_in[0];
    const int*   pos = (const int*)d_in[1];
    const float* Wq  = (const float*)d_in[2];
    const float* Wo  = (const float*)d_in[3];
    float* out = (float*)d_out;

    unsigned short *p_xh, *p_xl, *p_wq, *p_wo, *p_gah, *p_gal;
    cudaGetSymbolAddress((void**)&p_xh,  xa_hi);
    cudaGetSymbolAddress((void**)&p_xl,  xa_lo);
    cudaGetSymbolAddress((void**)&p_wq,  wq_h);
    cudaGetSymbolAddress((void**)&p_wo,  wo_h);
    cudaGetSymbolAddress((void**)&p_gah, ga_hi);
    cudaGetSymbolAddress((void**)&p_gal, ga_lo);

    const int GEMM_SMEM = STAGES * STG_BYTES;   // 98304

    // 0) fp16 conversions
    int n4x = (Bn * Tn * Dn) / 4;
    split_kernel<<<(n4x + 255) / 256, 256>>>(x, p_xh, p_xl, n4x);
    int n4wq = (3 * Dn * Dn) / 4;
    conv_kernel<<<(n4wq + 255) / 256, 256>>>(Wq, p_wq, n4wq);
    int n4wo = (Dn * Dn) / 4;
    conv_kernel<<<(n4wo + 255) / 256, 256>>>(Wo, p_wo, n4wo);

    // 1) QKV projection -> qkvh (+qkvl for q)
    cudaFuncSetAttribute(tc_gemm<0, 3072>,
                         cudaFuncAttributeMaxDynamicSharedMemorySize, GEMM_SMEM);
    tc_gemm<0, 3072><<<dim3(24, 64), 256, GEMM_SMEM>>>(p_xh, p_xl, p_wq, nullptr);

    // 2) tensor-core flash attention (128 q-rows / block) -> ga_hi/ga_lo
    cudaFuncSetAttribute(attn_mma,
                         cudaFuncAttributeMaxDynamicSharedMemorySize, ATTN_SMEM_SZ);
    attn_mma<<<dim3(Tn / 128, Bn * Hn), 256, ATTN_SMEM_SZ>>>(pos);

    // 3) output projection -> d_out
    cudaFuncSetAttribute(tc_gemm<1, 1024>,
                         cudaFuncAttributeMaxDynamicSharedMemorySize, GEMM_SMEM);
    tc_gemm<1, 1024><<<dim3(8, 64), 256, GEMM_SMEM>>>(p_gah, p_gal, p_wo, out);
}

// round 8
// speedup vs baseline: 1.4636x; 1.1088x over previous
#include <cuda_runtime.h>
#include <cuda_fp16.h>
#include <math.h>
#include <stdint.h>

// Problem constants
#define Bn 4
#define Tn 2048
#define Dn 1024
#define Hn 16
#define HDn 64
#define QKV_STRIDE (Bn * Hn * Tn * HDn)   // 8388608 elems per q/k/v

// ---------------------------------------------------------------------------
// Device scratch (no cudaMalloc allowed).  All u16 = fp16 bits.
// ---------------------------------------------------------------------------
__device__ unsigned short qkvh[3ull * QKV_STRIDE];      // [3][B][H][T][HD] fp16 hi (k,v: single)
__device__ unsigned short qkvl[3ull * QKV_STRIDE];      // fp16 lo (only q section used)
__device__ unsigned short xa_hi[(size_t)Bn * Tn * Dn];  // x split [8192][1024]
__device__ unsigned short xa_lo[(size_t)Bn * Tn * Dn];
__device__ unsigned short wq_h[(size_t)3 * Dn * Dn];    // Wqkv fp16 (native K-major)
__device__ unsigned short wo_h[(size_t)Dn * Dn];        // Wout fp16
__device__ unsigned short ga_hi[(size_t)Bn * Tn * Dn];  // attention out split
__device__ unsigned short ga_lo[(size_t)Bn * Tn * Dn];

// ---------------------------------------------------------------------------
// PTX helpers (non-arch-suffixed; valid on plain sm_103 target)
// ---------------------------------------------------------------------------
__device__ __forceinline__ uint32_t s2u(const void* p) {
    uint32_t a;
    asm("{ .reg .u64 t; cvta.to.shared.u64 t, %1; cvt.u32.u64 %0, t; }"
        : "=r"(a) : "l"(p));
    return a;
}
__device__ __forceinline__ void cpa16(uint32_t d, const void* s) {
    asm volatile("cp.async.cg.shared.global [%0], [%1], 16;"
                 :: "r"(d), "l"(s) : "memory");
}
__device__ __forceinline__ void cpa_commit() {
    asm volatile("cp.async.commit_group;" ::: "memory");
}
template<int N>
__device__ __forceinline__ void cpa_wait() {
    asm volatile("cp.async.wait_group %0;" :: "n"(N) : "memory");
}
__device__ __forceinline__ void ldsm4(uint32_t* r, uint32_t a) {
    asm volatile("ldmatrix.sync.aligned.m8n8.x4.shared.b16 {%0,%1,%2,%3}, [%4];"
        : "=r"(r[0]), "=r"(r[1]), "=r"(r[2]), "=r"(r[3]) : "r"(a));
}
__device__ __forceinline__ void ldsm4t(uint32_t* r, uint32_t a) {
    asm volatile("ldmatrix.sync.aligned.m8n8.x4.trans.shared.b16 {%0,%1,%2,%3}, [%4];"
        : "=r"(r[0]), "=r"(r[1]), "=r"(r[2]), "=r"(r[3]) : "r"(a));
}
__device__ __forceinline__ void mma16816(float* d, const uint32_t* a, const uint32_t* b) {
    asm volatile(
        "mma.sync.aligned.m16n8k16.row.col.f32.f16.f16.f32 "
        "{%0,%1,%2,%3}, {%4,%5,%6,%7}, {%8,%9}, {%0,%1,%2,%3};"
        : "+f"(d[0]), "+f"(d[1]), "+f"(d[2]), "+f"(d[3])
        : "r"(a[0]), "r"(a[1]), "r"(a[2]), "r"(a[3]), "r"(b[0]), "r"(b[1]));
}
// pack two f32 into f16x2: low half <- a, high half <- c
__device__ __forceinline__ uint32_t pack_hf2(float a, float c) {
    uint32_t d;
    asm("cvt.rn.f16x2.f32 %0, %1, %2;" : "=r"(d) : "f"(c), "f"(a));
    return d;
}

// Swizzles
#define SWA(o) ((o) ^ ((((o) >> 7) & 3) << 4))   // 64B rows (GEMM A bufs)
#define SWB(o) ((o) ^ ((((o) >> 8) & 7) << 4))   // 256B rows (GEMM B buf)
#define SW128(o) ((o) ^ ((((o) >> 7) & 7) << 4)) // 128B rows (attention)

// ---------------------------------------------------------------------------
// fp32 -> (fp16 hi, fp16 lo)
// ---------------------------------------------------------------------------
__device__ __forceinline__ void split1(float v, unsigned short& h, unsigned short& l) {
    __half hb = __float2half_rn(v);
    float r = v - __half2float(hb);
    __half lb = __float2half_rn(r);
    h = reinterpret_cast<unsigned short&>(hb);
    l = reinterpret_cast<unsigned short&>(lb);
}

__global__ __launch_bounds__(256)
void split_kernel(const float* __restrict__ in, unsigned short* __restrict__ hi,
                  unsigned short* __restrict__ lo, int n4)
{
    int i = blockIdx.x * 256 + threadIdx.x;
    if (i >= n4) return;
    float4 v = ((const float4*)in)[i];
    ushort4 h, l;
    split1(v.x, h.x, l.x);
    split1(v.y, h.y, l.y);
    split1(v.z, h.z, l.z);
    split1(v.w, h.w, l.w);
    ((ushort4*)hi)[i] = h;
    ((ushort4*)lo)[i] = l;
}

// fp32 -> single fp16 (weights)
__global__ __launch_bounds__(256)
void conv_kernel(const float* __restrict__ in, unsigned short* __restrict__ hi, int n4)
{
    int i = blockIdx.x * 256 + threadIdx.x;
    if (i >= n4) return;
    float4 v = ((const float4*)in)[i];
    __half a = __float2half_rn(v.x), b = __float2half_rn(v.y);
    __half c = __float2half_rn(v.z), d = __float2half_rn(v.w);
    ushort4 h;
    h.x = reinterpret_cast<unsigned short&>(a);
    h.y = reinterpret_cast<unsigned short&>(b);
    h.z = reinterpret_cast<unsigned short&>(c);
    h.w = reinterpret_cast<unsigned short&>(d);
    ((ushort4*)hi)[i] = h;
}

// ---------------------------------------------------------------------------
// fp16x2 GEMM via mma.sync: D[8192][NN] = (Ah+Al)[8192][1024] @ Bh[1024][NN]
// 128x128 CTA tile, BK=32, 4-stage cp.async pipeline, 8 warps (4m x 2n),
// warp tile 32x64.  One sync per k-block.  2 CTAs/SM enforced (<=128 regs).
// MODE 0: scatter into qkvh (+qkvl for q).  MODE 1: fp32 write to Cout.
// ---------------------------------------------------------------------------
#define BK 32
#define NKB2 32
#define STAGES 4
#define ABUF 8192                     // 128 x 32 fp16
#define BBUF 8192                     // 32 x 128 fp16
#define STG_BYTES (2 * ABUF + BBUF)   // 24576

template<int MODE, int NN>
__global__ __launch_bounds__(256, 2)
void tc_gemm(const unsigned short* __restrict__ Ah, const unsigned short* __restrict__ Al,
             const unsigned short* __restrict__ Bh, float* __restrict__ Cout)
{
    extern __shared__ __align__(1024) unsigned char gsm[];
    const uint32_t sbase = s2u(gsm);
    const int tid = threadIdx.x;
    const int lane = tid & 31, wid = tid >> 5;
    const int wm = wid & 3, wn = wid >> 2;
    const int bm = blockIdx.y * 128, bn = blockIdx.x * 128;

    const unsigned short* Abases[2] = { Ah + (size_t)bm * 1024, Al + (size_t)bm * 1024 };
    const unsigned short* Bbase = Bh + bn;

    auto load_stage = [&](int st, int kb) {
        uint32_t sb = sbase + st * STG_BYTES;
#pragma unroll
        for (int sp = 0; sp < 2; sp++) {
#pragma unroll
            for (int i = 0; i < 2; i++) {
                int id = i * 256 + tid;          // 0..511
                int r = id >> 2, c = id & 3;
                cpa16(sb + sp * ABUF + SWA(r * 64 + c * 16),
                      Abases[sp] + (size_t)r * 1024 + kb * BK + c * 8);
            }
        }
#pragma unroll
        for (int i = 0; i < 2; i++) {
            int id = i * 256 + tid;
            int rk = id >> 4, cc = id & 15;
            cpa16(sb + 2 * ABUF + SWB(rk * 256 + cc * 16),
                  Bbase + (size_t)(kb * BK + rk) * NN + cc * 8);
        }
    };

    float acc[2][8][4];
#pragma unroll
    for (int mt = 0; mt < 2; mt++)
#pragma unroll
        for (int nt = 0; nt < 8; nt++)
#pragma unroll
            for (int q = 0; q < 4; q++) acc[mt][nt][q] = 0.f;

    load_stage(0, 0); cpa_commit();
    load_stage(1, 1); cpa_commit();
    load_stage(2, 2); cpa_commit();

    const int a_lr = lane & 15;
    const int a_hk = (lane >> 4) << 4;

    for (int kb = 0; kb < NKB2; kb++) {
        const int cur = kb & 3;
        if (kb < NKB2 - 2) cpa_wait<2>();
        else if (kb == NKB2 - 2) cpa_wait<1>();
        else cpa_wait<0>();
        __syncthreads();
        // stage (kb+3)&3 was last read at iter kb-1; the barrier above seals it.
        if (kb + 3 < NKB2) { load_stage((kb + 3) & 3, kb + 3); cpa_commit(); }

        uint32_t sb = sbase + cur * STG_BYTES;
#pragma unroll
        for (int ks = 0; ks < 2; ks++) {
            uint32_t afr[2][2][4];
#pragma unroll
            for (int sp = 0; sp < 2; sp++)
#pragma unroll
                for (int mt = 0; mt < 2; mt++) {
                    int r = wm * 32 + mt * 16 + a_lr;
                    ldsm4(afr[sp][mt], sb + sp * ABUF + SWA(r * 64 + ks * 32 + a_hk));
                }
            uint32_t bfr[8][2];
#pragma unroll
            for (int nt2 = 0; nt2 < 4; nt2++) {
                int kk = ks * 16 + a_lr;
                int nb = wn * 128 + nt2 * 32 + a_hk;
                uint32_t t[4];
                ldsm4t(t, sb + 2 * ABUF + SWB(kk * 256 + nb));
                bfr[nt2 * 2][0] = t[0]; bfr[nt2 * 2][1] = t[1];
                bfr[nt2 * 2 + 1][0] = t[2]; bfr[nt2 * 2 + 1][1] = t[3];
            }
#pragma unroll
            for (int mt = 0; mt < 2; mt++)
#pragma unroll
                for (int nt = 0; nt < 8; nt++) {
                    mma16816(acc[mt][nt], afr[0][mt], bfr[nt]);
                    mma16816(acc[mt][nt], afr[1][mt], bfr[nt]);
                }
        }
    }

    const int gid = lane >> 2, tg = lane & 3;
#pragma unroll
    for (int mt = 0; mt < 2; mt++)
#pragma unroll
        for (int nt = 0; nt < 8; nt++) {
            int row0 = bm + wm * 32 + mt * 16 + gid;
            int col = bn + wn * 64 + nt * 8 + tg * 2;
#pragma unroll
            for (int half = 0; half < 2; half++) {
                int row = row0 + half * 8;
                float v0 = acc[mt][nt][half * 2], v1 = acc[mt][nt][half * 2 + 1];
                if (MODE == 0) {
                    int s = col >> 10, h = (col >> 6) & 15, d = col & 63;
                    int b = row >> 11, t = row & 2047;
                    size_t idx = (size_t)s * QKV_STRIDE +
                                 (((size_t)(b * Hn + h) * Tn + t) << 6) + d;
                    unsigned short h0, l0, h1, l1;
                    split1(v0, h0, l0);
                    split1(v1, h1, l1);
                    *(uint32_t*)&qkvh[idx] = (uint32_t)h0 | ((uint32_t)h1 << 16);
                    if (s == 0)
                        *(uint32_t*)&qkvl[idx] = (uint32_t)l0 | ((uint32_t)l1 << 16);
                } else {
                    *(float2*)&Cout[(size_t)row * NN + col] = make_float2(v0, v1);
                }
            }
        }
}

// ---------------------------------------------------------------------------
// Tensor-core flash attention, fp16x2 scheme.
// Q split hi/lo (exact); K,V single fp16.  256 threads = 8 warps; 128 q rows.
// ---------------------------------------------------------------------------
#define AQ_OFF 0                     // Q hi 16KB (128 rows x 128B)
#define AQL_OFF 16384                // Q lo 16KB
#define AKV_OFF 32768                // 2 stages x (K 8KB + V 8KB)
#define APOS_OFF (32768 + 32768)     // 65536
#define ATTN_SMEM_SZ (32768 + 32768 + 512)

__global__ __launch_bounds__(256)
void attn_mma(const int* __restrict__ pos)
{
    extern __shared__ __align__(1024) unsigned char am[];
    const uint32_t sb = s2u(am);
    const int tid = threadIdx.x, lane = tid & 31, wm = tid >> 5;   // wm 0..7
    const int b = blockIdx.y >> 4, h = blockIdx.y & 15;
    const int i0 = blockIdx.x * 128;

    const size_t bh_off = ((size_t)(b * Hn + h) * Tn) << 6;
    const unsigned short* Qhg = qkvh + bh_off + ((size_t)i0 << 6);
    const unsigned short* Qlg = qkvl + bh_off + ((size_t)i0 << 6);
    const unsigned short* Khg = qkvh + (size_t)QKV_STRIDE + bh_off;
    const unsigned short* Vhg = qkvh + 2ull * QKV_STRIDE + bh_off;
    const int* posb = pos + b * Tn;

    // Q tile (128 rows, hi+lo) -> smem
#pragma unroll
    for (int i = 0; i < 4; i++) {
        int id = tid + i * 256;            // 0..1023
        int r = id >> 3, c = id & 7;
        cpa16(sb + AQ_OFF + SW128(r * 128 + c * 16), Qhg + (size_t)r * 64 + c * 8);
        cpa16(sb + AQL_OFF + SW128(r * 128 + c * 16), Qlg + (size_t)r * 64 + c * 8);
    }
    cpa_commit();

    auto load_kv = [&](int st, int j0) {
        uint32_t base = sb + AKV_OFF + st * 16384;
        const unsigned short* srcs[2] = {
            Khg + ((size_t)j0 << 6), Vhg + ((size_t)j0 << 6) };
#pragma unroll
        for (int buf = 0; buf < 2; buf++)
#pragma unroll
            for (int i = 0; i < 2; i++) {
                int id = tid + i * 256;      // 0..511
                int r = id >> 3, c = id & 7;
                cpa16(base + buf * 8192 + SW128(r * 128 + c * 16),
                      srcs[buf] + (size_t)r * 64 + c * 8);
            }
        if (tid < 16)
            cpa16(sb + APOS_OFF + st * 256 + tid * 16, posb + j0 + tid * 4);
    };

    load_kv(0, 0);
    cpa_commit();

    cpa_wait<1>();
    __syncthreads();
    const int a_lr = lane & 15, a_hk = (lane >> 4) << 4;
    uint32_t qfh[4][4], qfl[4][4];
#pragma unroll
    for (int ks = 0; ks < 4; ks++) {
        int r = wm * 16 + a_lr;
        ldsm4(qfh[ks], sb + AQ_OFF + SW128(r * 128 + ks * 32 + a_hk));
        ldsm4(qfl[ks], sb + AQL_OFF + SW128(r * 128 + ks * 32 + a_hk));
    }

    const int pq0 = posb[i0 + wm * 16 + (lane >> 2)];
    const int pq1 = posb[i0 + wm * 16 + (lane >> 2) + 8];
    const int pqmax = posb[i0 + 127];
    const int jcol = 2 * (lane & 3);

    float m0 = -3e38f, m1 = -3e38f, l0 = 0.f, l1 = 0.f;
    float oacc[8][4];
#pragma unroll
    for (int nt = 0; nt < 8; nt++)
#pragma unroll
        for (int q = 0; q < 4; q++) oacc[nt][q] = 0.f;

    const float CS = 0.18033688011112042f;   // 0.125 * log2(e)

    int jb = 0, st = 0;
    for (;;) {
        int next = jb + 64;
        bool hn = (next < Tn) && (posb[next] <= pqmax);

        cpa_wait<0>();          // current stage fully resident
        __syncthreads();        // seals last iter's reads of stage st^1
        if (hn) { load_kv(st ^ 1, next); cpa_commit(); }

        const uint32_t kb_ = sb + AKV_OFF + st * 16384;
        const int* pkp = (const int*)(am + APOS_OFF + st * 256);

        float sacc[8][4];
#pragma unroll
        for (int nt = 0; nt < 8; nt++)
#pragma unroll
            for (int q = 0; q < 4; q++) sacc[nt][q] = 0.f;

#pragma unroll
        for (int ks = 0; ks < 4; ks++) {
            uint32_t kf[4][4];
            const int g = lane >> 3;
            const int krow = (g >> 1) * 8 + (lane & 7);
            const int kchk = ks * 32 + (g & 1) * 16;
#pragma unroll
            for (int call = 0; call < 4; call++) {
                uint32_t off = SW128((call * 16 + krow) * 128 + kchk);
                ldsm4(kf[call], kb_ + off);
            }
#pragma unroll
            for (int nt = 0; nt < 8; nt++) {
                const int c = nt >> 1, hf = (nt & 1) * 2;
                mma16816(sacc[nt], qfh[ks], &kf[c][hf]);
                mma16816(sacc[nt], qfl[ks], &kf[c][hf]);
            }
        }

        float mx0 = m0, mx1 = m1;
#pragma unroll
        for (int nt = 0; nt < 8; nt++) {
            int pk0 = pkp[nt * 8 + jcol], pk1 = pkp[nt * 8 + jcol + 1];
            float v0 = (pq0 < pk0) ? -3e38f : sacc[nt][0] * CS;
            float v1 = (pq0 < pk1) ? -3e38f : sacc[nt][1] * CS;
            float v2 = (pq1 < pk0) ? -3e38f : sacc[nt][2] * CS;
            float v3 = (pq1 < pk1) ? -3e38f : sacc[nt][3] * CS;
            sacc[nt][0] = v0; sacc[nt][1] = v1;
            sacc[nt][2] = v2; sacc[nt][3] = v3;
            mx0 = fmaxf(mx0, fmaxf(v0, v1));
            mx1 = fmaxf(mx1, fmaxf(v2, v3));
        }
        mx0 = fmaxf(mx0, __shfl_xor_sync(0xffffffffu, mx0, 1));
        mx0 = fmaxf(mx0, __shfl_xor_sync(0xffffffffu, mx0, 2));
        mx1 = fmaxf(mx1, __shfl_xor_sync(0xffffffffu, mx1, 1));
        mx1 = fmaxf(mx1, __shfl_xor_sync(0xffffffffu, mx1, 2));
        float al0 = exp2f(m0 - mx0), al1 = exp2f(m1 - mx1);
        m0 = mx0; m1 = mx1;

        float s0 = 0.f, s1 = 0.f;
#pragma unroll
        for (int nt = 0; nt < 8; nt++) {
            float p0 = exp2f(sacc[nt][0] - mx0);
            float p1 = exp2f(sacc[nt][1] - mx0);
            float p2 = exp2f(sacc[nt][2] - mx1);
            float p3 = exp2f(sacc[nt][3] - mx1);
            sacc[nt][0] = p0; sacc[nt][1] = p1;
            sacc[nt][2] = p2; sacc[nt][3] = p3;
            s0 += p0 + p1; s1 += p2 + p3;
        }
        s0 += __shfl_xor_sync(0xffffffffu, s0, 1);
        s0 += __shfl_xor_sync(0xffffffffu, s0, 2);
        s1 += __shfl_xor_sync(0xffffffffu, s1, 1);
        s1 += __shfl_xor_sync(0xffffffffu, s1, 2);
        l0 = l0 * al0 + s0;
        l1 = l1 * al1 + s1;
#pragma unroll
        for (int nt = 0; nt < 8; nt++) {
            oacc[nt][0] *= al0; oacc[nt][1] *= al0;
            oacc[nt][2] *= al1; oacc[nt][3] *= al1;
        }

        const uint32_t vb = kb_ + 8192;
#pragma unroll
        for (int kt = 0; kt < 4; kt++) {
            uint32_t ph[4], pl[4];
#pragma unroll
            for (int q = 0; q < 4; q++) {
                const float* src = (q < 2) ? sacc[2 * kt] : sacc[2 * kt + 1];
                float a = src[(q & 1) * 2], c = src[(q & 1) * 2 + 1];
                __half ha = __float2half_rn(a), hc = __float2half_rn(c);
                ph[q] = (uint32_t)reinterpret_cast<unsigned short&>(ha) |
                        ((uint32_t)reinterpret_cast<unsigned short&>(hc) << 16);
                pl[q] = pack_hf2(a - __half2float(ha), c - __half2float(hc));
            }
            uint32_t vf[4][4];
#pragma unroll
            for (int call = 0; call < 4; call++) {
                uint32_t off = SW128((kt * 16 + a_lr) * 128 + call * 32 + a_hk);
                ldsm4t(vf[call], vb + off);
            }
#pragma unroll
            for (int nt = 0; nt < 8; nt++) {
                const int c = nt >> 1, hf = (nt & 1) * 2;
                mma16816(oacc[nt], ph, &vf[c][hf]);
                mma16816(oacc[nt], pl, &vf[c][hf]);
            }
        }

        if (!hn) break;
        jb = next; st ^= 1;
    }

    float inv0 = 1.f / l0, inv1 = 1.f / l1;
    int t0r = i0 + wm * 16 + (lane >> 2);
#pragma unroll
    for (int nt = 0; nt < 8; nt++) {
        int col = h * 64 + nt * 8 + jcol;
#pragma unroll
        for (int half = 0; half < 2; half++) {
            int t = t0r + half * 8;
            float inv = half ? inv1 : inv0;
            float v0 = oacc[nt][half * 2] * inv;
            float v1 = oacc[nt][half * 2 + 1] * inv;
            unsigned short h0, lw0, h1, lw1;
            split1(v0, h0, lw0);
            split1(v1, h1, lw1);
            size_t idx = ((size_t)b * Tn + t) * Dn + col;
            *(uint32_t*)&ga_hi[idx] = (uint32_t)h0 | ((uint32_t)h1 << 16);
            *(uint32_t*)&ga_lo[idx] = (uint32_t)lw0 | ((uint32_t)lw1 << 16);
        }
    }
}

// ---------------------------------------------------------------------------
extern "C" void kernel_launch(void* const* d_in, const int* in_sizes, int n_in,
                              void* d_out, int out_size)
{
    const float* x   = (const float*)d_in[0];
    const int*   pos = (const int*)d_in[1];
    const float* Wq  = (const float*)d_in[2];
    const float* Wo  = (const float*)d_in[3];
    float* out = (float*)d_out;

    unsigned short *p_xh, *p_xl, *p_wq, *p_wo, *p_gah, *p_gal;
    cudaGetSymbolAddress((void**)&p_xh,  xa_hi);
    cudaGetSymbolAddress((void**)&p_xl,  xa_lo);
    cudaGetSymbolAddress((void**)&p_wq,  wq_h);
    cudaGetSymbolAddress((void**)&p_wo,  wo_h);
    cudaGetSymbolAddress((void**)&p_gah, ga_hi);
    cudaGetSymbolAddress((void**)&p_gal, ga_lo);

    const int GEMM_SMEM = STAGES * STG_BYTES;   // 98304

    // 0) fp16 conversions
    int n4x = (Bn * Tn * Dn) / 4;
    split_kernel<<<(n4x + 255) / 256, 256>>>(x, p_xh, p_xl, n4x);
    int n4wq = (3 * Dn * Dn) / 4;
    conv_kernel<<<(n4wq + 255) / 256, 256>>>(Wq, p_wq, n4wq);
    int n4wo = (Dn * Dn) / 4;
    conv_kernel<<<(n4wo + 255) / 256, 256>>>(Wo, p_wo, n4wo);

    // 1) QKV projection -> qkvh (+qkvl for q)
    cudaFuncSetAttribute(tc_gemm<0, 3072>,
                         cudaFuncAttributeMaxDynamicSharedMemorySize, GEMM_SMEM);
    tc_gemm<0, 3072><<<dim3(24, 64), 256, GEMM_SMEM>>>(p_xh, p_xl, p_wq, nullptr);

    // 2) tensor-core flash attention (128 q-rows / block) -> ga_hi/ga_lo
    cudaFuncSetAttribute(attn_mma,
                         cudaFuncAttributeMaxDynamicSharedMemorySize, ATTN_SMEM_SZ);
    attn_mma<<<dim3(Tn / 128, Bn * Hn), 256, ATTN_SMEM_SZ>>>(pos);

    // 3) output projection -> d_out
    cudaFuncSetAttribute(tc_gemm<1, 1024>,
                         cudaFuncAttributeMaxDynamicSharedMemorySize, GEMM_SMEM);
    tc_gemm<1, 1024><<<dim3(8, 64), 256, GEMM_SMEM>>>(p_gah, p_gal, p_wo, out);
}

// round 9
// speedup vs baseline: 1.6533x; 1.1296x over previous
#include <cuda_runtime.h>
#include <cuda_fp16.h>
#include <math.h>
#include <stdint.h>

// Problem constants
#define Bn 4
#define Tn 2048
#define Dn 1024
#define Hn 16
#define HDn 64
#define QKV_STRIDE (Bn * Hn * Tn * HDn)   // 8388608 elems per q/k/v

// ---------------------------------------------------------------------------
// Device scratch (no cudaMalloc allowed).  All u16 = fp16 bits.
// ---------------------------------------------------------------------------
__device__ unsigned short qkvh[3ull * QKV_STRIDE];      // [3][B][H][T][HD] fp16 hi (k,v: single)
__device__ unsigned short qkvl[3ull * QKV_STRIDE];      // fp16 lo (only q section used)
__device__ unsigned short xa_hi[(size_t)Bn * Tn * Dn];  // x split [8192][1024]
__device__ unsigned short xa_lo[(size_t)Bn * Tn * Dn];
__device__ unsigned short wq_h[(size_t)3 * Dn * Dn];    // Wqkv fp16 (native K-major)
__device__ unsigned short wo_h[(size_t)Dn * Dn];        // Wout fp16
__device__ unsigned short ga_hi[(size_t)Bn * Tn * Dn];  // attention out split
__device__ unsigned short ga_lo[(size_t)Bn * Tn * Dn];

// ---------------------------------------------------------------------------
// PTX helpers (non-arch-suffixed; valid on plain sm_103 target)
// ---------------------------------------------------------------------------
__device__ __forceinline__ uint32_t s2u(const void* p) {
    uint32_t a;
    asm("{ .reg .u64 t; cvta.to.shared.u64 t, %1; cvt.u32.u64 %0, t; }"
        : "=r"(a) : "l"(p));
    return a;
}
__device__ __forceinline__ void cpa16(uint32_t d, const void* s) {
    asm volatile("cp.async.cg.shared.global [%0], [%1], 16;"
                 :: "r"(d), "l"(s) : "memory");
}
__device__ __forceinline__ void cpa_commit() {
    asm volatile("cp.async.commit_group;" ::: "memory");
}
template<int N>
__device__ __forceinline__ void cpa_wait() {
    asm volatile("cp.async.wait_group %0;" :: "n"(N) : "memory");
}
__device__ __forceinline__ void ldsm4(uint32_t* r, uint32_t a) {
    asm volatile("ldmatrix.sync.aligned.m8n8.x4.shared.b16 {%0,%1,%2,%3}, [%4];"
        : "=r"(r[0]), "=r"(r[1]), "=r"(r[2]), "=r"(r[3]) : "r"(a));
}
__device__ __forceinline__ void ldsm4t(uint32_t* r, uint32_t a) {
    asm volatile("ldmatrix.sync.aligned.m8n8.x4.trans.shared.b16 {%0,%1,%2,%3}, [%4];"
        : "=r"(r[0]), "=r"(r[1]), "=r"(r[2]), "=r"(r[3]) : "r"(a));
}
__device__ __forceinline__ void mma16816(float* d, const uint32_t* a, const uint32_t* b) {
    asm volatile(
        "mma.sync.aligned.m16n8k16.row.col.f32.f16.f16.f32 "
        "{%0,%1,%2,%3}, {%4,%5,%6,%7}, {%8,%9}, {%0,%1,%2,%3};"
        : "+f"(d[0]), "+f"(d[1]), "+f"(d[2]), "+f"(d[3])
        : "r"(a[0]), "r"(a[1]), "r"(a[2]), "r"(a[3]), "r"(b[0]), "r"(b[1]));
}

// Swizzles
#define SWA(o) ((o) ^ ((((o) >> 7) & 3) << 4))   // 64B rows (GEMM A bufs)
#define SWB(o) ((o) ^ ((((o) >> 8) & 7) << 4))   // 256B rows (GEMM B buf)
#define SW128(o) ((o) ^ ((((o) >> 7) & 7) << 4)) // 128B rows (attention)

// ---------------------------------------------------------------------------
// fp32 -> (fp16 hi, fp16 lo)
// ---------------------------------------------------------------------------
__device__ __forceinline__ void split1(float v, unsigned short& h, unsigned short& l) {
    __half hb = __float2half_rn(v);
    float r = v - __half2float(hb);
    __half lb = __float2half_rn(r);
    h = reinterpret_cast<unsigned short&>(hb);
    l = reinterpret_cast<unsigned short&>(lb);
}

__global__ __launch_bounds__(256)
void split_kernel(const float* __restrict__ in, unsigned short* __restrict__ hi,
                  unsigned short* __restrict__ lo, int n4)
{
    int i = blockIdx.x * 256 + threadIdx.x;
    if (i >= n4) return;
    float4 v = ((const float4*)in)[i];
    ushort4 h, l;
    split1(v.x, h.x, l.x);
    split1(v.y, h.y, l.y);
    split1(v.z, h.z, l.z);
    split1(v.w, h.w, l.w);
    ((ushort4*)hi)[i] = h;
    ((ushort4*)lo)[i] = l;
}

// fp32 -> single fp16 (weights)
__global__ __launch_bounds__(256)
void conv_kernel(const float* __restrict__ in, unsigned short* __restrict__ hi, int n4)
{
    int i = blockIdx.x * 256 + threadIdx.x;
    if (i >= n4) return;
    float4 v = ((const float4*)in)[i];
    __half a = __float2half_rn(v.x), b = __float2half_rn(v.y);
    __half c = __float2half_rn(v.z), d = __float2half_rn(v.w);
    ushort4 h;
    h.x = reinterpret_cast<unsigned short&>(a);
    h.y = reinterpret_cast<unsigned short&>(b);
    h.z = reinterpret_cast<unsigned short&>(c);
    h.w = reinterpret_cast<unsigned short&>(d);
    ((ushort4*)hi)[i] = h;
}

// ---------------------------------------------------------------------------
// fp16x2 GEMM via mma.sync: D[8192][NN] = (Ah+Al)[8192][1024] @ Bh[1024][NN]
// 128x128 CTA tile, BK=32, 4-stage cp.async pipeline, 8 warps (4m x 2n),
// warp tile 32x64.  One sync per k-block.  2 CTAs/SM enforced (<=128 regs).
// MODE 0: scatter into qkvh (+qkvl for q).  MODE 1: fp32 write to Cout.
// ---------------------------------------------------------------------------
#define BK 32
#define NKB2 32
#define STAGES 4
#define ABUF 8192                     // 128 x 32 fp16
#define BBUF 8192                     // 32 x 128 fp16
#define STG_BYTES (2 * ABUF + BBUF)   // 24576

template<int MODE, int NN>
__global__ __launch_bounds__(256, 2)
void tc_gemm(const unsigned short* __restrict__ Ah, const unsigned short* __restrict__ Al,
             const unsigned short* __restrict__ Bh, float* __restrict__ Cout)
{
    extern __shared__ __align__(1024) unsigned char gsm[];
    const uint32_t sbase = s2u(gsm);
    const int tid = threadIdx.x;
    const int lane = tid & 31, wid = tid >> 5;
    const int wm = wid & 3, wn = wid >> 2;
    const int bm = blockIdx.y * 128, bn = blockIdx.x * 128;

    const unsigned short* Abases[2] = { Ah + (size_t)bm * 1024, Al + (size_t)bm * 1024 };
    const unsigned short* Bbase = Bh + bn;

    auto load_stage = [&](int st, int kb) {
        uint32_t sb = sbase + st * STG_BYTES;
#pragma unroll
        for (int sp = 0; sp < 2; sp++) {
#pragma unroll
            for (int i = 0; i < 2; i++) {
                int id = i * 256 + tid;          // 0..511
                int r = id >> 2, c = id & 3;
                cpa16(sb + sp * ABUF + SWA(r * 64 + c * 16),
                      Abases[sp] + (size_t)r * 1024 + kb * BK + c * 8);
            }
        }
#pragma unroll
        for (int i = 0; i < 2; i++) {
            int id = i * 256 + tid;
            int rk = id >> 4, cc = id & 15;
            cpa16(sb + 2 * ABUF + SWB(rk * 256 + cc * 16),
                  Bbase + (size_t)(kb * BK + rk) * NN + cc * 8);
        }
    };

    float acc[2][8][4];
#pragma unroll
    for (int mt = 0; mt < 2; mt++)
#pragma unroll
        for (int nt = 0; nt < 8; nt++)
#pragma unroll
            for (int q = 0; q < 4; q++) acc[mt][nt][q] = 0.f;

    load_stage(0, 0); cpa_commit();
    load_stage(1, 1); cpa_commit();
    load_stage(2, 2); cpa_commit();

    const int a_lr = lane & 15;
    const int a_hk = (lane >> 4) << 4;

    for (int kb = 0; kb < NKB2; kb++) {
        const int cur = kb & 3;
        if (kb < NKB2 - 2) cpa_wait<2>();
        else if (kb == NKB2 - 2) cpa_wait<1>();
        else cpa_wait<0>();
        __syncthreads();
        // stage (kb+3)&3 was last read at iter kb-1; the barrier above seals it.
        if (kb + 3 < NKB2) { load_stage((kb + 3) & 3, kb + 3); cpa_commit(); }

        uint32_t sb = sbase + cur * STG_BYTES;
#pragma unroll
        for (int ks = 0; ks < 2; ks++) {
            uint32_t afr[2][2][4];
#pragma unroll
            for (int sp = 0; sp < 2; sp++)
#pragma unroll
                for (int mt = 0; mt < 2; mt++) {
                    int r = wm * 32 + mt * 16 + a_lr;
                    ldsm4(afr[sp][mt], sb + sp * ABUF + SWA(r * 64 + ks * 32 + a_hk));
                }
            uint32_t bfr[8][2];
#pragma unroll
            for (int nt2 = 0; nt2 < 4; nt2++) {
                int kk = ks * 16 + a_lr;
                int nb = wn * 128 + nt2 * 32 + a_hk;
                uint32_t t[4];
                ldsm4t(t, sb + 2 * ABUF + SWB(kk * 256 + nb));
                bfr[nt2 * 2][0] = t[0]; bfr[nt2 * 2][1] = t[1];
                bfr[nt2 * 2 + 1][0] = t[2]; bfr[nt2 * 2 + 1][1] = t[3];
            }
#pragma unroll
            for (int mt = 0; mt < 2; mt++)
#pragma unroll
                for (int nt = 0; nt < 8; nt++) {
                    mma16816(acc[mt][nt], afr[0][mt], bfr[nt]);
                    mma16816(acc[mt][nt], afr[1][mt], bfr[nt]);
                }
        }
    }

    const int gid = lane >> 2, tg = lane & 3;
#pragma unroll
    for (int mt = 0; mt < 2; mt++)
#pragma unroll
        for (int nt = 0; nt < 8; nt++) {
            int row0 = bm + wm * 32 + mt * 16 + gid;
            int col = bn + wn * 64 + nt * 8 + tg * 2;
#pragma unroll
            for (int half = 0; half < 2; half++) {
                int row = row0 + half * 8;
                float v0 = acc[mt][nt][half * 2], v1 = acc[mt][nt][half * 2 + 1];
                if (MODE == 0) {
                    int s = col >> 10, h = (col >> 6) & 15, d = col & 63;
                    int b = row >> 11, t = row & 2047;
                    size_t idx = (size_t)s * QKV_STRIDE +
                                 (((size_t)(b * Hn + h) * Tn + t) << 6) + d;
                    unsigned short h0, l0, h1, l1;
                    split1(v0, h0, l0);
                    split1(v1, h1, l1);
                    *(uint32_t*)&qkvh[idx] = (uint32_t)h0 | ((uint32_t)h1 << 16);
                    if (s == 0)
                        *(uint32_t*)&qkvl[idx] = (uint32_t)l0 | ((uint32_t)l1 << 16);
                } else {
                    *(float2*)&Cout[(size_t)row * NN + col] = make_float2(v0, v1);
                }
            }
        }
}

// ---------------------------------------------------------------------------
// Tensor-core flash attention, fp16 scheme.
// Q split hi/lo (QK^T two-term); K,V single fp16; P single fp16 (PV one-term).
// 256 threads = 8 warps; 128 q rows per block.  2 CTAs/SM target.
// ---------------------------------------------------------------------------
#define AQ_OFF 0                     // Q hi 16KB (128 rows x 128B)
#define AQL_OFF 16384                // Q lo 16KB
#define AKV_OFF 32768                // 2 stages x (K 8KB + V 8KB)
#define APOS_OFF (32768 + 32768)     // 65536
#define ATTN_SMEM_SZ (32768 + 32768 + 512)

__global__ __launch_bounds__(256, 2)
void attn_mma(const int* __restrict__ pos)
{
    extern __shared__ __align__(1024) unsigned char am[];
    const uint32_t sb = s2u(am);
    const int tid = threadIdx.x, lane = tid & 31, wm = tid >> 5;   // wm 0..7
    const int b = blockIdx.y >> 4, h = blockIdx.y & 15;
    const int i0 = blockIdx.x * 128;

    const size_t bh_off = ((size_t)(b * Hn + h) * Tn) << 6;
    const unsigned short* Qhg = qkvh + bh_off + ((size_t)i0 << 6);
    const unsigned short* Qlg = qkvl + bh_off + ((size_t)i0 << 6);
    const unsigned short* Khg = qkvh + (size_t)QKV_STRIDE + bh_off;
    const unsigned short* Vhg = qkvh + 2ull * QKV_STRIDE + bh_off;
    const int* posb = pos + b * Tn;

    // Q tile (128 rows, hi+lo) -> smem
#pragma unroll
    for (int i = 0; i < 4; i++) {
        int id = tid + i * 256;            // 0..1023
        int r = id >> 3, c = id & 7;
        cpa16(sb + AQ_OFF + SW128(r * 128 + c * 16), Qhg + (size_t)r * 64 + c * 8);
        cpa16(sb + AQL_OFF + SW128(r * 128 + c * 16), Qlg + (size_t)r * 64 + c * 8);
    }
    cpa_commit();

    auto load_kv = [&](int st, int j0) {
        uint32_t base = sb + AKV_OFF + st * 16384;
        const unsigned short* srcs[2] = {
            Khg + ((size_t)j0 << 6), Vhg + ((size_t)j0 << 6) };
#pragma unroll
        for (int buf = 0; buf < 2; buf++)
#pragma unroll
            for (int i = 0; i < 2; i++) {
                int id = tid + i * 256;      // 0..511
                int r = id >> 3, c = id & 7;
                cpa16(base + buf * 8192 + SW128(r * 128 + c * 16),
                      srcs[buf] + (size_t)r * 64 + c * 8);
            }
        if (tid < 16)
            cpa16(sb + APOS_OFF + st * 256 + tid * 16, posb + j0 + tid * 4);
    };

    load_kv(0, 0);
    cpa_commit();

    cpa_wait<1>();
    __syncthreads();
    const int a_lr = lane & 15, a_hk = (lane >> 4) << 4;
    uint32_t qfh[4][4];
#pragma unroll
    for (int ks = 0; ks < 4; ks++) {
        int r = wm * 16 + a_lr;
        ldsm4(qfh[ks], sb + AQ_OFF + SW128(r * 128 + ks * 32 + a_hk));
    }

    const int pq0 = posb[i0 + wm * 16 + (lane >> 2)];
    const int pq1 = posb[i0 + wm * 16 + (lane >> 2) + 8];
    const int pqmax = posb[i0 + 127];
    const int jcol = 2 * (lane & 3);

    float m0 = -3e38f, m1 = -3e38f, l0 = 0.f, l1 = 0.f;
    float oacc[8][4];
#pragma unroll
    for (int nt = 0; nt < 8; nt++)
#pragma unroll
        for (int q = 0; q < 4; q++) oacc[nt][q] = 0.f;

    const float CS = 0.18033688011112042f;   // 0.125 * log2(e)

    int jb = 0, st = 0;
    for (;;) {
        int next = jb + 64;
        bool hn = (next < Tn) && (posb[next] <= pqmax);

        cpa_wait<0>();          // current stage fully resident
        __syncthreads();        // seals last iter's reads of stage st^1
        if (hn) { load_kv(st ^ 1, next); cpa_commit(); }

        const uint32_t kb_ = sb + AKV_OFF + st * 16384;
        const int* pkp = (const int*)(am + APOS_OFF + st * 256);

        float sacc[8][4];
#pragma unroll
        for (int nt = 0; nt < 8; nt++)
#pragma unroll
            for (int q = 0; q < 4; q++) sacc[nt][q] = 0.f;

#pragma unroll
        for (int ks = 0; ks < 4; ks++) {
            uint32_t kf[4][4];
            const int g = lane >> 3;
            const int krow = (g >> 1) * 8 + (lane & 7);
            const int kchk = ks * 32 + (g & 1) * 16;
#pragma unroll
            for (int call = 0; call < 4; call++) {
                uint32_t off = SW128((call * 16 + krow) * 128 + kchk);
                ldsm4(kf[call], kb_ + off);
            }
            // Q-lo fragment reloaded per ks (frees 16 registers vs holding)
            uint32_t qfl[4];
            {
                int r = wm * 16 + a_lr;
                ldsm4(qfl, sb + AQL_OFF + SW128(r * 128 + ks * 32 + a_hk));
            }
#pragma unroll
            for (int nt = 0; nt < 8; nt++) {
                const int c = nt >> 1, hf = (nt & 1) * 2;
                mma16816(sacc[nt], qfh[ks], &kf[c][hf]);
                mma16816(sacc[nt], qfl, &kf[c][hf]);
            }
        }

        float mx0 = m0, mx1 = m1;
#pragma unroll
        for (int nt = 0; nt < 8; nt++) {
            int pk0 = pkp[nt * 8 + jcol], pk1 = pkp[nt * 8 + jcol + 1];
            float v0 = (pq0 < pk0) ? -3e38f : sacc[nt][0] * CS;
            float v1 = (pq0 < pk1) ? -3e38f : sacc[nt][1] * CS;
            float v2 = (pq1 < pk0) ? -3e38f : sacc[nt][2] * CS;
            float v3 = (pq1 < pk1) ? -3e38f : sacc[nt][3] * CS;
            sacc[nt][0] = v0; sacc[nt][1] = v1;
            sacc[nt][2] = v2; sacc[nt][3] = v3;
            mx0 = fmaxf(mx0, fmaxf(v0, v1));
            mx1 = fmaxf(mx1, fmaxf(v2, v3));
        }
        mx0 = fmaxf(mx0, __shfl_xor_sync(0xffffffffu, mx0, 1));
        mx0 = fmaxf(mx0, __shfl_xor_sync(0xffffffffu, mx0, 2));
        mx1 = fmaxf(mx1, __shfl_xor_sync(0xffffffffu, mx1, 1));
        mx1 = fmaxf(mx1, __shfl_xor_sync(0xffffffffu, mx1, 2));
        float al0 = exp2f(m0 - mx0), al1 = exp2f(m1 - mx1);
        m0 = mx0; m1 = mx1;

        float s0 = 0.f, s1 = 0.f;
#pragma unroll
        for (int nt = 0; nt < 8; nt++) {
            float p0 = exp2f(sacc[nt][0] - mx0);
            float p1 = exp2f(sacc[nt][1] - mx0);
            float p2 = exp2f(sacc[nt][2] - mx1);
            float p3 = exp2f(sacc[nt][3] - mx1);
            sacc[nt][0] = p0; sacc[nt][1] = p1;
            sacc[nt][2] = p2; sacc[nt][3] = p3;
            s0 += p0 + p1; s1 += p2 + p3;
        }
        s0 += __shfl_xor_sync(0xffffffffu, s0, 1);
        s0 += __shfl_xor_sync(0xffffffffu, s0, 2);
        s1 += __shfl_xor_sync(0xffffffffu, s1, 1);
        s1 += __shfl_xor_sync(0xffffffffu, s1, 2);
        l0 = l0 * al0 + s0;
        l1 = l1 * al1 + s1;
#pragma unroll
        for (int nt = 0; nt < 8; nt++) {
            oacc[nt][0] *= al0; oacc[nt][1] *= al0;
            oacc[nt][2] *= al1; oacc[nt][3] *= al1;
        }

        // O += P V, single fp16 P term (P in [0,1]; rounding ~2.4e-4 rel,
        // below the already-accepted V rounding error)
        const uint32_t vb = kb_ + 8192;
#pragma unroll
        for (int kt = 0; kt < 4; kt++) {
            uint32_t ph[4];
#pragma unroll
            for (int q = 0; q < 4; q++) {
                const float* src = (q < 2) ? sacc[2 * kt] : sacc[2 * kt + 1];
                float a = src[(q & 1) * 2], c = src[(q & 1) * 2 + 1];
                __half ha = __float2half_rn(a), hc = __float2half_rn(c);
                ph[q] = (uint32_t)reinterpret_cast<unsigned short&>(ha) |
                        ((uint32_t)reinterpret_cast<unsigned short&>(hc) << 16);
            }
            uint32_t vf[4][4];
#pragma unroll
            for (int call = 0; call < 4; call++) {
                uint32_t off = SW128((kt * 16 + a_lr) * 128 + call * 32 + a_hk);
                ldsm4t(vf[call], vb + off);
            }
#pragma unroll
            for (int nt = 0; nt < 8; nt++) {
                const int c = nt >> 1, hf = (nt & 1) * 2;
                mma16816(oacc[nt], ph, &vf[c][hf]);
            }
        }

        if (!hn) break;
        jb = next; st ^= 1;
    }

    float inv0 = 1.f / l0, inv1 = 1.f / l1;
    int t0r = i0 + wm * 16 + (lane >> 2);
#pragma unroll
    for (int nt = 0; nt < 8; nt++) {
        int col = h * 64 + nt * 8 + jcol;
#pragma unroll
        for (int half = 0; half < 2; half++) {
            int t = t0r + half * 8;
            float inv = half ? inv1 : inv0;
            float v0 = oacc[nt][half * 2] * inv;
            float v1 = oacc[nt][half * 2 + 1] * inv;
            unsigned short h0, lw0, h1, lw1;
            split1(v0, h0, lw0);
            split1(v1, h1, lw1);
            size_t idx = ((size_t)b * Tn + t) * Dn + col;
            *(uint32_t*)&ga_hi[idx] = (uint32_t)h0 | ((uint32_t)h1 << 16);
            *(uint32_t*)&ga_lo[idx] = (uint32_t)lw0 | ((uint32_t)lw1 << 16);
        }
    }
}

// ---------------------------------------------------------------------------
extern "C" void kernel_launch(void* const* d_in, const int* in_sizes, int n_in,
                              void* d_out, int out_size)
{
    const float* x   = (const float*)d_in[0];
    const int*   pos = (const int*)d_in[1];
    const float* Wq  = (const float*)d_in[2];
    const float* Wo  = (const float*)d_in[3];
    float* out = (float*)d_out;

    unsigned short *p_xh, *p_xl, *p_wq, *p_wo, *p_gah, *p_gal;
    cudaGetSymbolAddress((void**)&p_xh,  xa_hi);
    cudaGetSymbolAddress((void**)&p_xl,  xa_lo);
    cudaGetSymbolAddress((void**)&p_wq,  wq_h);
    cudaGetSymbolAddress((void**)&p_wo,  wo_h);
    cudaGetSymbolAddress((void**)&p_gah, ga_hi);
    cudaGetSymbolAddress((void**)&p_gal, ga_lo);

    const int GEMM_SMEM = STAGES * STG_BYTES;   // 98304

    // 0) fp16 conversions
    int n4x = (Bn * Tn * Dn) / 4;
    split_kernel<<<(n4x + 255) / 256, 256>>>(x, p_xh, p_xl, n4x);
    int n4wq = (3 * Dn * Dn) / 4;
    conv_kernel<<<(n4wq + 255) / 256, 256>>>(Wq, p_wq, n4wq);
    int n4wo = (Dn * Dn) / 4;
    conv_kernel<<<(n4wo + 255) / 256, 256>>>(Wo, p_wo, n4wo);

    // 1) QKV projection -> qkvh (+qkvl for q)
    cudaFuncSetAttribute(tc_gemm<0, 3072>,
                         cudaFuncAttributeMaxDynamicSharedMemorySize, GEMM_SMEM);
    tc_gemm<0, 3072><<<dim3(24, 64), 256, GEMM_SMEM>>>(p_xh, p_xl, p_wq, nullptr);

    // 2) tensor-core flash attention (128 q-rows / block) -> ga_hi/ga_lo
    cudaFuncSetAttribute(attn_mma,
                         cudaFuncAttributeMaxDynamicSharedMemorySize, ATTN_SMEM_SZ);
    attn_mma<<<dim3(Tn / 128, Bn * Hn), 256, ATTN_SMEM_SZ>>>(pos);

    // 3) output projection -> d_out
    cudaFuncSetAttribute(tc_gemm<1, 1024>,
                         cudaFuncAttributeMaxDynamicSharedMemorySize, GEMM_SMEM);
    tc_gemm<1, 1024><<<dim3(8, 64), 256, GEMM_SMEM>>>(p_gah, p_gal, p_wo, out);
}

// round 10
// speedup vs baseline: 2.2180x; 1.3415x over previous
#include <cuda_runtime.h>
#include <cuda_fp16.h>
#include <math.h>
#include <stdint.h>

// Problem constants
#define Bn 4
#define Tn 2048
#define Dn 1024
#define Hn 16
#define HDn 64
#define QKV_STRIDE (Bn * Hn * Tn * HDn)   // 8388608 elems per q/k/v

// ---------------------------------------------------------------------------
// Device scratch (no cudaMalloc allowed).  All u16 = fp16 bits.
// ---------------------------------------------------------------------------
__device__ unsigned short qkvh[3ull * QKV_STRIDE];      // [3][B][H][T][HD] fp16 (k,v single)
__device__ unsigned short qkvl[3ull * QKV_STRIDE];      // fp16 lo (only q section used)
__device__ unsigned short xa_h[(size_t)Bn * Tn * Dn];   // x fp16 [8192][1024]
__device__ unsigned short wq_h[(size_t)3 * Dn * Dn];    // Wqkv fp16 (native K-major)
__device__ unsigned short wo_h[(size_t)Dn * Dn];        // Wout fp16
__device__ unsigned short ga_h[(size_t)Bn * Tn * Dn];   // attention out fp16

// ---------------------------------------------------------------------------
// PTX helpers (non-arch-suffixed; valid on plain sm_103 target)
// ---------------------------------------------------------------------------
__device__ __forceinline__ uint32_t s2u(const void* p) {
    uint32_t a;
    asm("{ .reg .u64 t; cvta.to.shared.u64 t, %1; cvt.u32.u64 %0, t; }"
        : "=r"(a) : "l"(p));
    return a;
}
__device__ __forceinline__ void cpa16(uint32_t d, const void* s) {
    asm volatile("cp.async.cg.shared.global [%0], [%1], 16;"
                 :: "r"(d), "l"(s) : "memory");
}
__device__ __forceinline__ void cpa_commit() {
    asm volatile("cp.async.commit_group;" ::: "memory");
}
template<int N>
__device__ __forceinline__ void cpa_wait() {
    asm volatile("cp.async.wait_group %0;" :: "n"(N) : "memory");
}
__device__ __forceinline__ void ldsm4(uint32_t* r, uint32_t a) {
    asm volatile("ldmatrix.sync.aligned.m8n8.x4.shared.b16 {%0,%1,%2,%3}, [%4];"
        : "=r"(r[0]), "=r"(r[1]), "=r"(r[2]), "=r"(r[3]) : "r"(a));
}
__device__ __forceinline__ void ldsm4t(uint32_t* r, uint32_t a) {
    asm volatile("ldmatrix.sync.aligned.m8n8.x4.trans.shared.b16 {%0,%1,%2,%3}, [%4];"
        : "=r"(r[0]), "=r"(r[1]), "=r"(r[2]), "=r"(r[3]) : "r"(a));
}
__device__ __forceinline__ void mma16816(float* d, const uint32_t* a, const uint32_t* b) {
    asm volatile(
        "mma.sync.aligned.m16n8k16.row.col.f32.f16.f16.f32 "
        "{%0,%1,%2,%3}, {%4,%5,%6,%7}, {%8,%9}, {%0,%1,%2,%3};"
        : "+f"(d[0]), "+f"(d[1]), "+f"(d[2]), "+f"(d[3])
        : "r"(a[0]), "r"(a[1]), "r"(a[2]), "r"(a[3]), "r"(b[0]), "r"(b[1]));
}

// Swizzles
#define SWB(o) ((o) ^ ((((o) >> 8) & 7) << 4))   // 256B rows (GEMM B buf)
#define SW128(o) ((o) ^ ((((o) >> 7) & 7) << 4)) // 128B rows (GEMM A buf + attention)

// ---------------------------------------------------------------------------
// fp32 -> (fp16 hi, fp16 lo)
// ---------------------------------------------------------------------------
__device__ __forceinline__ void split1(float v, unsigned short& h, unsigned short& l) {
    __half hb = __float2half_rn(v);
    float r = v - __half2float(hb);
    __half lb = __float2half_rn(r);
    h = reinterpret_cast<unsigned short&>(hb);
    l = reinterpret_cast<unsigned short&>(lb);
}

// fp32 -> single fp16
__global__ __launch_bounds__(256)
void conv_kernel(const float* __restrict__ in, unsigned short* __restrict__ hi, int n4)
{
    int i = blockIdx.x * 256 + threadIdx.x;
    if (i >= n4) return;
    float4 v = ((const float4*)in)[i];
    __half a = __float2half_rn(v.x), b = __float2half_rn(v.y);
    __half c = __float2half_rn(v.z), d = __float2half_rn(v.w);
    ushort4 h;
    h.x = reinterpret_cast<unsigned short&>(a);
    h.y = reinterpret_cast<unsigned short&>(b);
    h.z = reinterpret_cast<unsigned short&>(c);
    h.w = reinterpret_cast<unsigned short&>(d);
    ((ushort4*)hi)[i] = h;
}

// ---------------------------------------------------------------------------
// Single-term fp16 GEMM via mma.sync: D[8192][NN] = Ah[8192][1024] @ Bh[1024][NN]
// 128x128 CTA tile, BK=64, 3-stage cp.async pipeline (32KB/stage), 8 warps
// (4m x 2n), warp tile 32x64, 64 MMAs per k-block, one sync per k-block.
// 2 CTAs/SM enforced.  MODE 0: scatter into qkvh (+qkvl for q).  MODE 1: fp32.
// ---------------------------------------------------------------------------
#define BK 64
#define NKB2 16                        // 1024 / 64
#define STAGES 3
#define ABUF 16384                     // 128 rows x 64 fp16 (128B rows)
#define BBUF 16384                     // 64 rows x 128 fp16 (256B rows)
#define STG_BYTES (ABUF + BBUF)        // 32768

template<int MODE, int NN>
__global__ __launch_bounds__(256, 2)
void tc_gemm(const unsigned short* __restrict__ Ah,
             const unsigned short* __restrict__ Bh, float* __restrict__ Cout)
{
    extern __shared__ __align__(1024) unsigned char gsm[];
    const uint32_t sbase = s2u(gsm);
    const int tid = threadIdx.x;
    const int lane = tid & 31, wid = tid >> 5;
    const int wm = wid & 3, wn = wid >> 2;
    const int bm = blockIdx.y * 128, bn = blockIdx.x * 128;

    const unsigned short* Abase = Ah + (size_t)bm * 1024;
    const unsigned short* Bbase = Bh + bn;

    auto load_stage = [&](int st, int kb) {
        uint32_t sb = sbase + st * STG_BYTES;
        // A: 128 rows x 8 16B-chunks = 1024 chunks
#pragma unroll
        for (int i = 0; i < 4; i++) {
            int id = i * 256 + tid;
            int r = id >> 3, c = id & 7;
            cpa16(sb + SW128(r * 128 + c * 16),
                  Abase + (size_t)r * 1024 + kb * BK + c * 8);
        }
        // B: 64 rows x 16 16B-chunks = 1024 chunks
#pragma unroll
        for (int i = 0; i < 4; i++) {
            int id = i * 256 + tid;
            int rk = id >> 4, cc = id & 15;
            cpa16(sb + ABUF + SWB(rk * 256 + cc * 16),
                  Bbase + (size_t)(kb * BK + rk) * NN + cc * 8);
        }
    };

    float acc[2][8][4];
#pragma unroll
    for (int mt = 0; mt < 2; mt++)
#pragma unroll
        for (int nt = 0; nt < 8; nt++)
#pragma unroll
            for (int q = 0; q < 4; q++) acc[mt][nt][q] = 0.f;

    load_stage(0, 0); cpa_commit();
    load_stage(1, 1); cpa_commit();

    const int a_lr = lane & 15;
    const int a_hk = (lane >> 4) << 4;

    for (int kb = 0; kb < NKB2; kb++) {
        const int cur = kb % STAGES;
        cpa_wait<1>();          // uniform: 2 groups pending before wait
        __syncthreads();
        if (kb + 2 < NKB2) load_stage((kb + 2) % STAGES, kb + 2);
        cpa_commit();           // unconditional (possibly empty group)

        uint32_t sb = sbase + cur * STG_BYTES;
#pragma unroll
        for (int ks = 0; ks < 4; ks++) {
            uint32_t afr[2][4];
#pragma unroll
            for (int mt = 0; mt < 2; mt++) {
                int r = wm * 32 + mt * 16 + a_lr;
                ldsm4(afr[mt], sb + SW128(r * 128 + ks * 32 + a_hk));
            }
            uint32_t bfr[8][2];
#pragma unroll
            for (int nt2 = 0; nt2 < 4; nt2++) {
                int kk = ks * 16 + a_lr;
                int nb = wn * 128 + nt2 * 32 + a_hk;
                uint32_t t[4];
                ldsm4t(t, sb + ABUF + SWB(kk * 256 + nb));
                bfr[nt2 * 2][0] = t[0]; bfr[nt2 * 2][1] = t[1];
                bfr[nt2 * 2 + 1][0] = t[2]; bfr[nt2 * 2 + 1][1] = t[3];
            }
#pragma unroll
            for (int mt = 0; mt < 2; mt++)
#pragma unroll
                for (int nt = 0; nt < 8; nt++)
                    mma16816(acc[mt][nt], afr[mt], bfr[nt]);
        }
    }

    const int gid = lane >> 2, tg = lane & 3;
#pragma unroll
    for (int mt = 0; mt < 2; mt++)
#pragma unroll
        for (int nt = 0; nt < 8; nt++) {
            int row0 = bm + wm * 32 + mt * 16 + gid;
            int col = bn + wn * 64 + nt * 8 + tg * 2;
#pragma unroll
            for (int half = 0; half < 2; half++) {
                int row = row0 + half * 8;
                float v0 = acc[mt][nt][half * 2], v1 = acc[mt][nt][half * 2 + 1];
                if (MODE == 0) {
                    int s = col >> 10, h = (col >> 6) & 15, d = col & 63;
                    int b = row >> 11, t = row & 2047;
                    size_t idx = (size_t)s * QKV_STRIDE +
                                 (((size_t)(b * Hn + h) * Tn + t) << 6) + d;
                    unsigned short h0, l0, h1, l1;
                    split1(v0, h0, l0);
                    split1(v1, h1, l1);
                    *(uint32_t*)&qkvh[idx] = (uint32_t)h0 | ((uint32_t)h1 << 16);
                    if (s == 0)
                        *(uint32_t*)&qkvl[idx] = (uint32_t)l0 | ((uint32_t)l1 << 16);
                } else {
                    *(float2*)&Cout[(size_t)row * NN + col] = make_float2(v0, v1);
                }
            }
        }
}

// ---------------------------------------------------------------------------
// Tensor-core flash attention, fp16 scheme.
// Q split hi/lo (QK^T two-term); K,V single fp16; P single fp16 (PV one-term).
// 256 threads = 8 warps; 128 q rows per block.  2 CTAs/SM.
// ---------------------------------------------------------------------------
#define AQ_OFF 0                     // Q hi 16KB (128 rows x 128B)
#define AQL_OFF 16384                // Q lo 16KB
#define AKV_OFF 32768                // 2 stages x (K 8KB + V 8KB)
#define APOS_OFF (32768 + 32768)     // 65536
#define ATTN_SMEM_SZ (32768 + 32768 + 512)

__global__ __launch_bounds__(256, 2)
void attn_mma(const int* __restrict__ pos)
{
    extern __shared__ __align__(1024) unsigned char am[];
    const uint32_t sb = s2u(am);
    const int tid = threadIdx.x, lane = tid & 31, wm = tid >> 5;   // wm 0..7
    const int b = blockIdx.y >> 4, h = blockIdx.y & 15;
    const int i0 = blockIdx.x * 128;

    const size_t bh_off = ((size_t)(b * Hn + h) * Tn) << 6;
    const unsigned short* Qhg = qkvh + bh_off + ((size_t)i0 << 6);
    const unsigned short* Qlg = qkvl + bh_off + ((size_t)i0 << 6);
    const unsigned short* Khg = qkvh + (size_t)QKV_STRIDE + bh_off;
    const unsigned short* Vhg = qkvh + 2ull * QKV_STRIDE + bh_off;
    const int* posb = pos + b * Tn;

    // Q tile (128 rows, hi+lo) -> smem
#pragma unroll
    for (int i = 0; i < 4; i++) {
        int id = tid + i * 256;            // 0..1023
        int r = id >> 3, c = id & 7;
        cpa16(sb + AQ_OFF + SW128(r * 128 + c * 16), Qhg + (size_t)r * 64 + c * 8);
        cpa16(sb + AQL_OFF + SW128(r * 128 + c * 16), Qlg + (size_t)r * 64 + c * 8);
    }
    cpa_commit();

    auto load_kv = [&](int st, int j0) {
        uint32_t base = sb + AKV_OFF + st * 16384;
        const unsigned short* srcs[2] = {
            Khg + ((size_t)j0 << 6), Vhg + ((size_t)j0 << 6) };
#pragma unroll
        for (int buf = 0; buf < 2; buf++)
#pragma unroll
            for (int i = 0; i < 2; i++) {
                int id = tid + i * 256;      // 0..511
                int r = id >> 3, c = id & 7;
                cpa16(base + buf * 8192 + SW128(r * 128 + c * 16),
                      srcs[buf] + (size_t)r * 64 + c * 8);
            }
        if (tid < 16)
            cpa16(sb + APOS_OFF + st * 256 + tid * 16, posb + j0 + tid * 4);
    };

    load_kv(0, 0);
    cpa_commit();

    cpa_wait<1>();
    __syncthreads();
    const int a_lr = lane & 15, a_hk = (lane >> 4) << 4;
    uint32_t qfh[4][4];
#pragma unroll
    for (int ks = 0; ks < 4; ks++) {
        int r = wm * 16 + a_lr;
        ldsm4(qfh[ks], sb + AQ_OFF + SW128(r * 128 + ks * 32 + a_hk));
    }

    const int pq0 = posb[i0 + wm * 16 + (lane >> 2)];
    const int pq1 = posb[i0 + wm * 16 + (lane >> 2) + 8];
    const int pqmax = posb[i0 + 127];
    const int jcol = 2 * (lane & 3);

    float m0 = -3e38f, m1 = -3e38f, l0 = 0.f, l1 = 0.f;
    float oacc[8][4];
#pragma unroll
    for (int nt = 0; nt < 8; nt++)
#pragma unroll
        for (int q = 0; q < 4; q++) oacc[nt][q] = 0.f;

    const float CS = 0.18033688011112042f;   // 0.125 * log2(e)

    int jb = 0, st = 0;
    for (;;) {
        int next = jb + 64;
        bool hn = (next < Tn) && (posb[next] <= pqmax);

        cpa_wait<0>();          // current stage fully resident
        __syncthreads();        // seals last iter's reads of stage st^1
        if (hn) { load_kv(st ^ 1, next); cpa_commit(); }

        const uint32_t kb_ = sb + AKV_OFF + st * 16384;
        const int* pkp = (const int*)(am + APOS_OFF + st * 256);

        float sacc[8][4];
#pragma unroll
        for (int nt = 0; nt < 8; nt++)
#pragma unroll
            for (int q = 0; q < 4; q++) sacc[nt][q] = 0.f;

#pragma unroll
        for (int ks = 0; ks < 4; ks++) {
            uint32_t kf[4][4];
            const int g = lane >> 3;
            const int krow = (g >> 1) * 8 + (lane & 7);
            const int kchk = ks * 32 + (g & 1) * 16;
#pragma unroll
            for (int call = 0; call < 4; call++) {
                uint32_t off = SW128((call * 16 + krow) * 128 + kchk);
                ldsm4(kf[call], kb_ + off);
            }
            uint32_t qfl[4];
            {
                int r = wm * 16 + a_lr;
                ldsm4(qfl, sb + AQL_OFF + SW128(r * 128 + ks * 32 + a_hk));
            }
#pragma unroll
            for (int nt = 0; nt < 8; nt++) {
                const int c = nt >> 1, hf = (nt & 1) * 2;
                mma16816(sacc[nt], qfh[ks], &kf[c][hf]);
                mma16816(sacc[nt], qfl, &kf[c][hf]);
            }
        }

        float mx0 = m0, mx1 = m1;
#pragma unroll
        for (int nt = 0; nt < 8; nt++) {
            int pk0 = pkp[nt * 8 + jcol], pk1 = pkp[nt * 8 + jcol + 1];
            float v0 = (pq0 < pk0) ? -3e38f : sacc[nt][0] * CS;
            float v1 = (pq0 < pk1) ? -3e38f : sacc[nt][1] * CS;
            float v2 = (pq1 < pk0) ? -3e38f : sacc[nt][2] * CS;
            float v3 = (pq1 < pk1) ? -3e38f : sacc[nt][3] * CS;
            sacc[nt][0] = v0; sacc[nt][1] = v1;
            sacc[nt][2] = v2; sacc[nt][3] = v3;
            mx0 = fmaxf(mx0, fmaxf(v0, v1));
            mx1 = fmaxf(mx1, fmaxf(v2, v3));
        }
        mx0 = fmaxf(mx0, __shfl_xor_sync(0xffffffffu, mx0, 1));
        mx0 = fmaxf(mx0, __shfl_xor_sync(0xffffffffu, mx0, 2));
        mx1 = fmaxf(mx1, __shfl_xor_sync(0xffffffffu, mx1, 1));
        mx1 = fmaxf(mx1, __shfl_xor_sync(0xffffffffu, mx1, 2));
        float al0 = exp2f(m0 - mx0), al1 = exp2f(m1 - mx1);
        m0 = mx0; m1 = mx1;

        float s0 = 0.f, s1 = 0.f;
#pragma unroll
        for (int nt = 0; nt < 8; nt++) {
            float p0 = exp2f(sacc[nt][0] - mx0);
            float p1 = exp2f(sacc[nt][1] - mx0);
            float p2 = exp2f(sacc[nt][2] - mx1);
            float p3 = exp2f(sacc[nt][3] - mx1);
            sacc[nt][0] = p0; sacc[nt][1] = p1;
            sacc[nt][2] = p2; sacc[nt][3] = p3;
            s0 += p0 + p1; s1 += p2 + p3;
        }
        s0 += __shfl_xor_sync(0xffffffffu, s0, 1);
        s0 += __shfl_xor_sync(0xffffffffu, s0, 2);
        s1 += __shfl_xor_sync(0xffffffffu, s1, 1);
        s1 += __shfl_xor_sync(0xffffffffu, s1, 2);
        l0 = l0 * al0 + s0;
        l1 = l1 * al1 + s1;
#pragma unroll
        for (int nt = 0; nt < 8; nt++) {
            oacc[nt][0] *= al0; oacc[nt][1] *= al0;
            oacc[nt][2] *= al1; oacc[nt][3] *= al1;
        }

        const uint32_t vb = kb_ + 8192;
#pragma unroll
        for (int kt = 0; kt < 4; kt++) {
            uint32_t ph[4];
#pragma unroll
            for (int q = 0; q < 4; q++) {
                const float* src = (q < 2) ? sacc[2 * kt] : sacc[2 * kt + 1];
                float a = src[(q & 1) * 2], c = src[(q & 1) * 2 + 1];
                __half ha = __float2half_rn(a), hc = __float2half_rn(c);
                ph[q] = (uint32_t)reinterpret_cast<unsigned short&>(ha) |
                        ((uint32_t)reinterpret_cast<unsigned short&>(hc) << 16);
            }
            uint32_t vf[4][4];
#pragma unroll
            for (int call = 0; call < 4; call++) {
                uint32_t off = SW128((kt * 16 + a_lr) * 128 + call * 32 + a_hk);
                ldsm4t(vf[call], vb + off);
            }
#pragma unroll
            for (int nt = 0; nt < 8; nt++) {
                const int c = nt >> 1, hf = (nt & 1) * 2;
                mma16816(oacc[nt], ph, &vf[c][hf]);
            }
        }

        if (!hn) break;
        jb = next; st ^= 1;
    }

    // Epilogue: normalize, write single fp16 to ga_h
    float inv0 = 1.f / l0, inv1 = 1.f / l1;
    int t0r = i0 + wm * 16 + (lane >> 2);
#pragma unroll
    for (int nt = 0; nt < 8; nt++) {
        int col = h * 64 + nt * 8 + jcol;
#pragma unroll
        for (int half = 0; half < 2; half++) {
            int t = t0r + half * 8;
            float inv = half ? inv1 : inv0;
            float v0 = oacc[nt][half * 2] * inv;
            float v1 = oacc[nt][half * 2 + 1] * inv;
            __half h0 = __float2half_rn(v0), h1 = __float2half_rn(v1);
            size_t idx = ((size_t)b * Tn + t) * Dn + col;
            *(uint32_t*)&ga_h[idx] =
                (uint32_t)reinterpret_cast<unsigned short&>(h0) |
                ((uint32_t)reinterpret_cast<unsigned short&>(h1) << 16);
        }
    }
}

// ---------------------------------------------------------------------------
extern "C" void kernel_launch(void* const* d_in, const int* in_sizes, int n_in,
                              void* d_out, int out_size)
{
    const float* x   = (const float*)d_in[0];
    const int*   pos = (const int*)d_in[1];
    const float* Wq  = (const float*)d_in[2];
    const float* Wo  = (const float*)d_in[3];
    float* out = (float*)d_out;

    unsigned short *p_xh, *p_wq, *p_wo, *p_gah;
    cudaGetSymbolAddress((void**)&p_xh,  xa_h);
    cudaGetSymbolAddress((void**)&p_wq,  wq_h);
    cudaGetSymbolAddress((void**)&p_wo,  wo_h);
    cudaGetSymbolAddress((void**)&p_gah, ga_h);

    const int GEMM_SMEM = STAGES * STG_BYTES;   // 98304

    // 0) fp16 conversions (single-term everywhere; splits happen in epilogues)
    int n4x = (Bn * Tn * Dn) / 4;
    conv_kernel<<<(n4x + 255) / 256, 256>>>(x, p_xh, n4x);
    int n4wq = (3 * Dn * Dn) / 4;
    conv_kernel<<<(n4wq + 255) / 256, 256>>>(Wq, p_wq, n4wq);
    int n4wo = (Dn * Dn) / 4;
    conv_kernel<<<(n4wo + 255) / 256, 256>>>(Wo, p_wo, n4wo);

    // 1) QKV projection -> qkvh (+qkvl for q)
    cudaFuncSetAttribute(tc_gemm<0, 3072>,
                         cudaFuncAttributeMaxDynamicSharedMemorySize, GEMM_SMEM);
    tc_gemm<0, 3072><<<dim3(24, 64), 256, GEMM_SMEM>>>(p_xh, p_wq, nullptr);

    // 2) tensor-core flash attention (128 q-rows / block) -> ga_h
    cudaFuncSetAttribute(attn_mma,
                         cudaFuncAttributeMaxDynamicSharedMemorySize, ATTN_SMEM_SZ);
    attn_mma<<<dim3(Tn / 128, Bn * Hn), 256, ATTN_SMEM_SZ>>>(pos);

    // 3) output projection -> d_out
    cudaFuncSetAttribute(tc_gemm<1, 1024>,
                         cudaFuncAttributeMaxDynamicSharedMemorySize, GEMM_SMEM);
    tc_gemm<1, 1024><<<dim3(8, 64), 256, GEMM_SMEM>>>(p_gah, p_wo, out);
}

// round 11
// speedup vs baseline: 2.3157x; 1.0441x over previous
#include <cuda_runtime.h>
#include <cuda_fp16.h>
#include <math.h>
#include <stdint.h>

// Problem constants
#define Bn 4
#define Tn 2048
#define Dn 1024
#define Hn 16
#define HDn 64
#define QKV_STRIDE (Bn * Hn * Tn * HDn)   // 8388608 elems per q/k/v

// ---------------------------------------------------------------------------
// Device scratch (no cudaMalloc allowed).  All u16 = fp16 bits.
// ---------------------------------------------------------------------------
__device__ unsigned short qkvh[3ull * QKV_STRIDE];      // [3][B][H][T][HD] fp16 (k,v single)
__device__ unsigned short qkvl[3ull * QKV_STRIDE];      // fp16 lo (only q section used)
__device__ unsigned short xa_h[(size_t)Bn * Tn * Dn];   // x fp16 [8192][1024]
__device__ unsigned short wq_h[(size_t)3 * Dn * Dn];    // Wqkv fp16 (native K-major)
__device__ unsigned short wo_h[(size_t)Dn * Dn];        // Wout fp16
__device__ unsigned short ga_h[(size_t)Bn * Tn * Dn];   // attention out fp16

// ---------------------------------------------------------------------------
// PTX helpers (non-arch-suffixed; valid on plain sm_103 target)
// ---------------------------------------------------------------------------
__device__ __forceinline__ uint32_t s2u(const void* p) {
    uint32_t a;
    asm("{ .reg .u64 t; cvta.to.shared.u64 t, %1; cvt.u32.u64 %0, t; }"
        : "=r"(a) : "l"(p));
    return a;
}
__device__ __forceinline__ void cpa16(uint32_t d, const void* s) {
    asm volatile("cp.async.cg.shared.global [%0], [%1], 16;"
                 :: "r"(d), "l"(s) : "memory");
}
__device__ __forceinline__ void cpa_commit() {
    asm volatile("cp.async.commit_group;" ::: "memory");
}
template<int N>
__device__ __forceinline__ void cpa_wait() {
    asm volatile("cp.async.wait_group %0;" :: "n"(N) : "memory");
}
__device__ __forceinline__ void ldsm4(uint32_t* r, uint32_t a) {
    asm volatile("ldmatrix.sync.aligned.m8n8.x4.shared.b16 {%0,%1,%2,%3}, [%4];"
        : "=r"(r[0]), "=r"(r[1]), "=r"(r[2]), "=r"(r[3]) : "r"(a));
}
__device__ __forceinline__ void ldsm4t(uint32_t* r, uint32_t a) {
    asm volatile("ldmatrix.sync.aligned.m8n8.x4.trans.shared.b16 {%0,%1,%2,%3}, [%4];"
        : "=r"(r[0]), "=r"(r[1]), "=r"(r[2]), "=r"(r[3]) : "r"(a));
}
__device__ __forceinline__ void mma16816(float* d, const uint32_t* a, const uint32_t* b) {
    asm volatile(
        "mma.sync.aligned.m16n8k16.row.col.f32.f16.f16.f32 "
        "{%0,%1,%2,%3}, {%4,%5,%6,%7}, {%8,%9}, {%0,%1,%2,%3};"
        : "+f"(d[0]), "+f"(d[1]), "+f"(d[2]), "+f"(d[3])
        : "r"(a[0]), "r"(a[1]), "r"(a[2]), "r"(a[3]), "r"(b[0]), "r"(b[1]));
}

// Swizzles
#define SWB(o) ((o) ^ ((((o) >> 8) & 7) << 4))   // 256B rows (GEMM B buf)
#define SW128(o) ((o) ^ ((((o) >> 7) & 7) << 4)) // 128B rows (GEMM A buf + attention)

// ---------------------------------------------------------------------------
// fp32 -> (fp16 hi, fp16 lo)
// ---------------------------------------------------------------------------
__device__ __forceinline__ void split1(float v, unsigned short& h, unsigned short& l) {
    __half hb = __float2half_rn(v);
    float r = v - __half2float(hb);
    __half lb = __float2half_rn(r);
    h = reinterpret_cast<unsigned short&>(hb);
    l = reinterpret_cast<unsigned short&>(lb);
}

// fp32 -> single fp16
__global__ __launch_bounds__(256)
void conv_kernel(const float* __restrict__ in, unsigned short* __restrict__ hi, int n4)
{
    int i = blockIdx.x * 256 + threadIdx.x;
    if (i >= n4) return;
    float4 v = ((const float4*)in)[i];
    __half a = __float2half_rn(v.x), b = __float2half_rn(v.y);
    __half c = __float2half_rn(v.z), d = __float2half_rn(v.w);
    ushort4 h;
    h.x = reinterpret_cast<unsigned short&>(a);
    h.y = reinterpret_cast<unsigned short&>(b);
    h.z = reinterpret_cast<unsigned short&>(c);
    h.w = reinterpret_cast<unsigned short&>(d);
    ((ushort4*)hi)[i] = h;
}

// ---------------------------------------------------------------------------
// Single-term fp16 GEMM via mma.sync: D[8192][NN] = Ah[8192][1024] @ Bh[1024][NN]
// 128x128 CTA tile, BK=64, 3-stage cp.async pipeline (32KB/stage), 8 warps
// (4m x 2n), warp tile 32x64, 64 MMAs per k-block, one sync per k-block.
// 2 CTAs/SM enforced.  MODE 0: scatter into qkvh (+qkvl for q).  MODE 1: fp32.
// ---------------------------------------------------------------------------
#define BK 64
#define NKB2 16                        // 1024 / 64
#define STAGES 3
#define ABUF 16384                     // 128 rows x 64 fp16 (128B rows)
#define BBUF 16384                     // 64 rows x 128 fp16 (256B rows)
#define STG_BYTES (ABUF + BBUF)        // 32768

template<int MODE, int NN>
__global__ __launch_bounds__(256, 2)
void tc_gemm(const unsigned short* __restrict__ Ah,
             const unsigned short* __restrict__ Bh, float* __restrict__ Cout)
{
    extern __shared__ __align__(1024) unsigned char gsm[];
    const uint32_t sbase = s2u(gsm);
    const int tid = threadIdx.x;
    const int lane = tid & 31, wid = tid >> 5;
    const int wm = wid & 3, wn = wid >> 2;
    const int bm = blockIdx.y * 128, bn = blockIdx.x * 128;

    const unsigned short* Abase = Ah + (size_t)bm * 1024;
    const unsigned short* Bbase = Bh + bn;

    auto load_stage = [&](int st, int kb) {
        uint32_t sb = sbase + st * STG_BYTES;
#pragma unroll
        for (int i = 0; i < 4; i++) {
            int id = i * 256 + tid;
            int r = id >> 3, c = id & 7;
            cpa16(sb + SW128(r * 128 + c * 16),
                  Abase + (size_t)r * 1024 + kb * BK + c * 8);
        }
#pragma unroll
        for (int i = 0; i < 4; i++) {
            int id = i * 256 + tid;
            int rk = id >> 4, cc = id & 15;
            cpa16(sb + ABUF + SWB(rk * 256 + cc * 16),
                  Bbase + (size_t)(kb * BK + rk) * NN + cc * 8);
        }
    };

    float acc[2][8][4];
#pragma unroll
    for (int mt = 0; mt < 2; mt++)
#pragma unroll
        for (int nt = 0; nt < 8; nt++)
#pragma unroll
            for (int q = 0; q < 4; q++) acc[mt][nt][q] = 0.f;

    load_stage(0, 0); cpa_commit();
    load_stage(1, 1); cpa_commit();

    const int a_lr = lane & 15;
    const int a_hk = (lane >> 4) << 4;

    for (int kb = 0; kb < NKB2; kb++) {
        const int cur = kb % STAGES;
        cpa_wait<1>();
        __syncthreads();
        if (kb + 2 < NKB2) load_stage((kb + 2) % STAGES, kb + 2);
        cpa_commit();

        uint32_t sb = sbase + cur * STG_BYTES;
#pragma unroll
        for (int ks = 0; ks < 4; ks++) {
            uint32_t afr[2][4];
#pragma unroll
            for (int mt = 0; mt < 2; mt++) {
                int r = wm * 32 + mt * 16 + a_lr;
                ldsm4(afr[mt], sb + SW128(r * 128 + ks * 32 + a_hk));
            }
            uint32_t bfr[8][2];
#pragma unroll
            for (int nt2 = 0; nt2 < 4; nt2++) {
                int kk = ks * 16 + a_lr;
                int nb = wn * 128 + nt2 * 32 + a_hk;
                uint32_t t[4];
                ldsm4t(t, sb + ABUF + SWB(kk * 256 + nb));
                bfr[nt2 * 2][0] = t[0]; bfr[nt2 * 2][1] = t[1];
                bfr[nt2 * 2 + 1][0] = t[2]; bfr[nt2 * 2 + 1][1] = t[3];
            }
#pragma unroll
            for (int mt = 0; mt < 2; mt++)
#pragma unroll
                for (int nt = 0; nt < 8; nt++)
                    mma16816(acc[mt][nt], afr[mt], bfr[nt]);
        }
    }

    const int gid = lane >> 2, tg = lane & 3;
#pragma unroll
    for (int mt = 0; mt < 2; mt++)
#pragma unroll
        for (int nt = 0; nt < 8; nt++) {
            int row0 = bm + wm * 32 + mt * 16 + gid;
            int col = bn + wn * 64 + nt * 8 + tg * 2;
#pragma unroll
            for (int half = 0; half < 2; half++) {
                int row = row0 + half * 8;
                float v0 = acc[mt][nt][half * 2], v1 = acc[mt][nt][half * 2 + 1];
                if (MODE == 0) {
                    int s = col >> 10, h = (col >> 6) & 15, d = col & 63;
                    int b = row >> 11, t = row & 2047;
                    size_t idx = (size_t)s * QKV_STRIDE +
                                 (((size_t)(b * Hn + h) * Tn + t) << 6) + d;
                    unsigned short h0, l0, h1, l1;
                    split1(v0, h0, l0);
                    split1(v1, h1, l1);
                    *(uint32_t*)&qkvh[idx] = (uint32_t)h0 | ((uint32_t)h1 << 16);
                    if (s == 0)
                        *(uint32_t*)&qkvl[idx] = (uint32_t)l0 | ((uint32_t)l1 << 16);
                } else {
                    *(float2*)&Cout[(size_t)row * NN + col] = make_float2(v0, v1);
                }
            }
        }
}

// ---------------------------------------------------------------------------
// Tensor-core flash attention, fp16 scheme.
// Q split hi/lo (QK^T two-term); K,V single fp16; P single fp16 (PV one-term).
// 256 threads = 8 warps; 128 q rows per block.  2 CTAs/SM.
// Softmax on raw logits (scale folded into exp via FFMA); mask-free fast path
// for strictly-below-diagonal kv blocks; descending tile order for wave tail.
// ---------------------------------------------------------------------------
#define AQ_OFF 0                     // Q hi 16KB (128 rows x 128B)
#define AQL_OFF 16384                // Q lo 16KB
#define AKV_OFF 32768                // 2 stages x (K 8KB + V 8KB)
#define APOS_OFF (32768 + 32768)     // 65536
#define ATTN_SMEM_SZ (32768 + 32768 + 512)

__global__ __launch_bounds__(256, 2)
void attn_mma(const int* __restrict__ pos)
{
    extern __shared__ __align__(1024) unsigned char am[];
    const uint32_t sb = s2u(am);
    const int tid = threadIdx.x, lane = tid & 31, wm = tid >> 5;   // wm 0..7
    const int b = blockIdx.y >> 4, h = blockIdx.y & 15;
    const int i0 = (15 - blockIdx.x) * 128;    // heavy tiles scheduled first

    const size_t bh_off = ((size_t)(b * Hn + h) * Tn) << 6;
    const unsigned short* Qhg = qkvh + bh_off + ((size_t)i0 << 6);
    const unsigned short* Qlg = qkvl + bh_off + ((size_t)i0 << 6);
    const unsigned short* Khg = qkvh + (size_t)QKV_STRIDE + bh_off;
    const unsigned short* Vhg = qkvh + 2ull * QKV_STRIDE + bh_off;
    const int* posb = pos + b * Tn;

    // Q tile (128 rows, hi+lo) -> smem
#pragma unroll
    for (int i = 0; i < 4; i++) {
        int id = tid + i * 256;            // 0..1023
        int r = id >> 3, c = id & 7;
        cpa16(sb + AQ_OFF + SW128(r * 128 + c * 16), Qhg + (size_t)r * 64 + c * 8);
        cpa16(sb + AQL_OFF + SW128(r * 128 + c * 16), Qlg + (size_t)r * 64 + c * 8);
    }
    cpa_commit();

    auto load_kv = [&](int st, int j0) {
        uint32_t base = sb + AKV_OFF + st * 16384;
        const unsigned short* srcs[2] = {
            Khg + ((size_t)j0 << 6), Vhg + ((size_t)j0 << 6) };
#pragma unroll
        for (int buf = 0; buf < 2; buf++)
#pragma unroll
            for (int i = 0; i < 2; i++) {
                int id = tid + i * 256;      // 0..511
                int r = id >> 3, c = id & 7;
                cpa16(base + buf * 8192 + SW128(r * 128 + c * 16),
                      srcs[buf] + (size_t)r * 64 + c * 8);
            }
        if (tid < 16)
            cpa16(sb + APOS_OFF + st * 256 + tid * 16, posb + j0 + tid * 4);
    };

    load_kv(0, 0);
    cpa_commit();

    cpa_wait<1>();
    __syncthreads();
    const int a_lr = lane & 15, a_hk = (lane >> 4) << 4;
    uint32_t qfh[4][4];
#pragma unroll
    for (int ks = 0; ks < 4; ks++) {
        int r = wm * 16 + a_lr;
        ldsm4(qfh[ks], sb + AQ_OFF + SW128(r * 128 + ks * 32 + a_hk));
    }

    const int pq0 = posb[i0 + wm * 16 + (lane >> 2)];
    const int pq1 = posb[i0 + wm * 16 + (lane >> 2) + 8];
    const int pqmin = posb[i0];
    const int pqmax = posb[i0 + 127];
    const int jcol = 2 * (lane & 3);

    float m0 = -3e38f, m1 = -3e38f, l0 = 0.f, l1 = 0.f;
    float oacc[8][4];
#pragma unroll
    for (int nt = 0; nt < 8; nt++)
#pragma unroll
        for (int q = 0; q < 4; q++) oacc[nt][q] = 0.f;

    const float CS = 0.18033688011112042f;   // 0.125 * log2(e)

    int jb = 0, st = 0;
    for (;;) {
        int next = jb + 64;
        bool hn = (next < Tn) && (posb[next] <= pqmax);

        cpa_wait<0>();          // current stage fully resident
        __syncthreads();        // seals last iter's reads of stage st^1
        if (hn) { load_kv(st ^ 1, next); cpa_commit(); }

        const uint32_t kb_ = sb + AKV_OFF + st * 16384;
        const int* pkp = (const int*)(am + APOS_OFF + st * 256);

        float sacc[8][4];
#pragma unroll
        for (int nt = 0; nt < 8; nt++)
#pragma unroll
            for (int q = 0; q < 4; q++) sacc[nt][q] = 0.f;

#pragma unroll
        for (int ks = 0; ks < 4; ks++) {
            uint32_t kf[4][4];
            const int g = lane >> 3;
            const int krow = (g >> 1) * 8 + (lane & 7);
            const int kchk = ks * 32 + (g & 1) * 16;
#pragma unroll
            for (int call = 0; call < 4; call++) {
                uint32_t off = SW128((call * 16 + krow) * 128 + kchk);
                ldsm4(kf[call], kb_ + off);
            }
            uint32_t qfl[4];
            {
                int r = wm * 16 + a_lr;
                ldsm4(qfl, sb + AQL_OFF + SW128(r * 128 + ks * 32 + a_hk));
            }
#pragma unroll
            for (int nt = 0; nt < 8; nt++) {
                const int c = nt >> 1, hf = (nt & 1) * 2;
                mma16816(sacc[nt], qfh[ks], &kf[c][hf]);
                mma16816(sacc[nt], qfl, &kf[c][hf]);
            }
        }

        // ---- online softmax on RAW logits; scale folded into exp ----
        const bool need_mask = (pkp[63] > pqmin);   // any pk > any pq possible?
        float mx0 = m0, mx1 = m1;
        if (need_mask) {
#pragma unroll
            for (int nt = 0; nt < 8; nt++) {
                int pk0 = pkp[nt * 8 + jcol], pk1 = pkp[nt * 8 + jcol + 1];
                float v0 = (pq0 < pk0) ? -3e38f : sacc[nt][0];
                float v1 = (pq0 < pk1) ? -3e38f : sacc[nt][1];
                float v2 = (pq1 < pk0) ? -3e38f : sacc[nt][2];
                float v3 = (pq1 < pk1) ? -3e38f : sacc[nt][3];
                sacc[nt][0] = v0; sacc[nt][1] = v1;
                sacc[nt][2] = v2; sacc[nt][3] = v3;
                mx0 = fmaxf(mx0, fmaxf(v0, v1));
                mx1 = fmaxf(mx1, fmaxf(v2, v3));
            }
        } else {
#pragma unroll
            for (int nt = 0; nt < 8; nt++) {
                mx0 = fmaxf(mx0, fmaxf(sacc[nt][0], sacc[nt][1]));
                mx1 = fmaxf(mx1, fmaxf(sacc[nt][2], sacc[nt][3]));
            }
        }
        mx0 = fmaxf(mx0, __shfl_xor_sync(0xffffffffu, mx0, 1));
        mx0 = fmaxf(mx0, __shfl_xor_sync(0xffffffffu, mx0, 2));
        mx1 = fmaxf(mx1, __shfl_xor_sync(0xffffffffu, mx1, 1));
        mx1 = fmaxf(mx1, __shfl_xor_sync(0xffffffffu, mx1, 2));
        float al0 = exp2f((m0 - mx0) * CS), al1 = exp2f((m1 - mx1) * CS);
        m0 = mx0; m1 = mx1;
        const float c0 = -mx0 * CS, c1 = -mx1 * CS;

        float s0 = 0.f, s1 = 0.f;
#pragma unroll
        for (int nt = 0; nt < 8; nt++) {
            float p0 = exp2f(fmaf(sacc[nt][0], CS, c0));
            float p1 = exp2f(fmaf(sacc[nt][1], CS, c0));
            float p2 = exp2f(fmaf(sacc[nt][2], CS, c1));
            float p3 = exp2f(fmaf(sacc[nt][3], CS, c1));
            sacc[nt][0] = p0; sacc[nt][1] = p1;
            sacc[nt][2] = p2; sacc[nt][3] = p3;
            s0 += p0 + p1; s1 += p2 + p3;
        }
        s0 += __shfl_xor_sync(0xffffffffu, s0, 1);
        s0 += __shfl_xor_sync(0xffffffffu, s0, 2);
        s1 += __shfl_xor_sync(0xffffffffu, s1, 1);
        s1 += __shfl_xor_sync(0xffffffffu, s1, 2);
        l0 = l0 * al0 + s0;
        l1 = l1 * al1 + s1;
#pragma unroll
        for (int nt = 0; nt < 8; nt++) {
            oacc[nt][0] *= al0; oacc[nt][1] *= al0;
            oacc[nt][2] *= al1; oacc[nt][3] *= al1;
        }

        const uint32_t vb = kb_ + 8192;
#pragma unroll
        for (int kt = 0; kt < 4; kt++) {
            uint32_t ph[4];
#pragma unroll
            for (int q = 0; q < 4; q++) {
                const float* src = (q < 2) ? sacc[2 * kt] : sacc[2 * kt + 1];
                float a = src[(q & 1) * 2], c = src[(q & 1) * 2 + 1];
                __half ha = __float2half_rn(a), hc = __float2half_rn(c);
                ph[q] = (uint32_t)reinterpret_cast<unsigned short&>(ha) |
                        ((uint32_t)reinterpret_cast<unsigned short&>(hc) << 16);
            }
            uint32_t vf[4][4];
#pragma unroll
            for (int call = 0; call < 4; call++) {
                uint32_t off = SW128((kt * 16 + a_lr) * 128 + call * 32 + a_hk);
                ldsm4t(vf[call], vb + off);
            }
#pragma unroll
            for (int nt = 0; nt < 8; nt++) {
                const int c = nt >> 1, hf = (nt & 1) * 2;
                mma16816(oacc[nt], ph, &vf[c][hf]);
            }
        }

        if (!hn) break;
        jb = next; st ^= 1;
    }

    // Epilogue: normalize, write single fp16 to ga_h
    float inv0 = 1.f / l0, inv1 = 1.f / l1;
    int t0r = i0 + wm * 16 + (lane >> 2);
#pragma unroll
    for (int nt = 0; nt < 8; nt++) {
        int col = h * 64 + nt * 8 + jcol;
#pragma unroll
        for (int half = 0; half < 2; half++) {
            int t = t0r + half * 8;
            float inv = half ? inv1 : inv0;
            float v0 = oacc[nt][half * 2] * inv;
            float v1 = oacc[nt][half * 2 + 1] * inv;
            __half h0 = __float2half_rn(v0), h1 = __float2half_rn(v1);
            size_t idx = ((size_t)b * Tn + t) * Dn + col;
            *(uint32_t*)&ga_h[idx] =
                (uint32_t)reinterpret_cast<unsigned short&>(h0) |
                ((uint32_t)reinterpret_cast<unsigned short&>(h1) << 16);
        }
    }
}

// ---------------------------------------------------------------------------
extern "C" void kernel_launch(void* const* d_in, const int* in_sizes, int n_in,
                              void* d_out, int out_size)
{
    const float* x   = (const float*)d_in[0];
    const int*   pos = (const int*)d_in[1];
    const float* Wq  = (const float*)d_in[2];
    const float* Wo  = (const float*)d_in[3];
    float* out = (float*)d_out;

    unsigned short *p_xh, *p_wq, *p_wo, *p_gah;
    cudaGetSymbolAddress((void**)&p_xh,  xa_h);
    cudaGetSymbolAddress((void**)&p_wq,  wq_h);
    cudaGetSymbolAddress((void**)&p_wo,  wo_h);
    cudaGetSymbolAddress((void**)&p_gah, ga_h);

    const int GEMM_SMEM = STAGES * STG_BYTES;   // 98304

    // 0) fp16 conversions
    int n4x = (Bn * Tn * Dn) / 4;
    conv_kernel<<<(n4x + 255) / 256, 256>>>(x, p_xh, n4x);
    int n4wq = (3 * Dn * Dn) / 4;
    conv_kernel<<<(n4wq + 255) / 256, 256>>>(Wq, p_wq, n4wq);
    int n4wo = (Dn * Dn) / 4;
    conv_kernel<<<(n4wo + 255) / 256, 256>>>(Wo, p_wo, n4wo);

    // 1) QKV projection -> qkvh (+qkvl for q)
    cudaFuncSetAttribute(tc_gemm<0, 3072>,
                         cudaFuncAttributeMaxDynamicSharedMemorySize, GEMM_SMEM);
    tc_gemm<0, 3072><<<dim3(24, 64), 256, GEMM_SMEM>>>(p_xh, p_wq, nullptr);

    // 2) tensor-core flash attention (128 q-rows / block) -> ga_h
    cudaFuncSetAttribute(attn_mma,
                         cudaFuncAttributeMaxDynamicSharedMemorySize, ATTN_SMEM_SZ);
    attn_mma<<<dim3(Tn / 128, Bn * Hn), 256, ATTN_SMEM_SZ>>>(pos);

    // 3) output projection -> d_out
    cudaFuncSetAttribute(tc_gemm<1, 1024>,
                         cudaFuncAttributeMaxDynamicSharedMemorySize, GEMM_SMEM);
    tc_gemm<1, 1024><<<dim3(8, 64), 256, GEMM_SMEM>>>(p_gah, p_wo, out);
}

// round 12
// speedup vs baseline: 2.6662x; 1.1513x over previous
#include <cuda_runtime.h>
#include <cuda_fp16.h>
#include <math.h>
#include <stdint.h>

// Problem constants
#define Bn 4
#define Tn 2048
#define Dn 1024
#define Hn 16
#define HDn 64
#define QKV_STRIDE (Bn * Hn * Tn * HDn)   // 8388608 elems per q/k/v

// ---------------------------------------------------------------------------
// Device scratch (no cudaMalloc allowed).  All u16 = fp16 bits.
// ---------------------------------------------------------------------------
__device__ unsigned short qkvh[3ull * QKV_STRIDE];      // [3][B][H][T][HD] fp16
__device__ unsigned short xa_h[(size_t)Bn * Tn * Dn];   // x fp16 [8192][1024]
__device__ unsigned short wq_h[(size_t)3 * Dn * Dn];    // Wqkv fp16 (native K-major)
__device__ unsigned short wo_h[(size_t)Dn * Dn];        // Wout fp16
__device__ unsigned short ga_h[(size_t)Bn * Tn * Dn];   // attention out fp16

// ---------------------------------------------------------------------------
// PTX helpers (non-arch-suffixed; valid on plain sm_103 target)
// ---------------------------------------------------------------------------
__device__ __forceinline__ uint32_t s2u(const void* p) {
    uint32_t a;
    asm("{ .reg .u64 t; cvta.to.shared.u64 t, %1; cvt.u32.u64 %0, t; }"
        : "=r"(a) : "l"(p));
    return a;
}
__device__ __forceinline__ void cpa16(uint32_t d, const void* s) {
    asm volatile("cp.async.cg.shared.global [%0], [%1], 16;"
                 :: "r"(d), "l"(s) : "memory");
}
__device__ __forceinline__ void cpa_commit() {
    asm volatile("cp.async.commit_group;" ::: "memory");
}
template<int N>
__device__ __forceinline__ void cpa_wait() {
    asm volatile("cp.async.wait_group %0;" :: "n"(N) : "memory");
}
__device__ __forceinline__ void ldsm4(uint32_t* r, uint32_t a) {
    asm volatile("ldmatrix.sync.aligned.m8n8.x4.shared.b16 {%0,%1,%2,%3}, [%4];"
        : "=r"(r[0]), "=r"(r[1]), "=r"(r[2]), "=r"(r[3]) : "r"(a));
}
__device__ __forceinline__ void ldsm4t(uint32_t* r, uint32_t a) {
    asm volatile("ldmatrix.sync.aligned.m8n8.x4.trans.shared.b16 {%0,%1,%2,%3}, [%4];"
        : "=r"(r[0]), "=r"(r[1]), "=r"(r[2]), "=r"(r[3]) : "r"(a));
}
__device__ __forceinline__ void mma16816(float* d, const uint32_t* a, const uint32_t* b) {
    asm volatile(
        "mma.sync.aligned.m16n8k16.row.col.f32.f16.f16.f32 "
        "{%0,%1,%2,%3}, {%4,%5,%6,%7}, {%8,%9}, {%0,%1,%2,%3};"
        : "+f"(d[0]), "+f"(d[1]), "+f"(d[2]), "+f"(d[3])
        : "r"(a[0]), "r"(a[1]), "r"(a[2]), "r"(a[3]), "r"(b[0]), "r"(b[1]));
}

// Swizzles
#define SWB(o) ((o) ^ ((((o) >> 8) & 7) << 4))   // 256B rows (GEMM B buf)
#define SW128(o) ((o) ^ ((((o) >> 7) & 7) << 4)) // 128B rows (GEMM A buf + attention)

// fp32 -> single fp16, fused over the three source arrays
__global__ __launch_bounds__(256)
void conv_fused_kernel(const float* __restrict__ x, unsigned short* __restrict__ xo,
                       const float* __restrict__ wq, unsigned short* __restrict__ wqo,
                       const float* __restrict__ wo, unsigned short* __restrict__ woo,
                       int nbx, int nbwq, int nbwo)
{
    const float* src;
    unsigned short* dst;
    int blk = blockIdx.x;
    if (blk < nbx) { src = x; dst = xo; }
    else if (blk < nbx + nbwq) { src = wq; dst = wqo; blk -= nbx; }
    else { src = wo; dst = woo; blk -= nbx + nbwq; }
    int i = blk * 256 + threadIdx.x;
    float4 v = ((const float4*)src)[i];
    __half a = __float2half_rn(v.x), b = __float2half_rn(v.y);
    __half c = __float2half_rn(v.z), d = __float2half_rn(v.w);
    ushort4 h;
    h.x = reinterpret_cast<unsigned short&>(a);
    h.y = reinterpret_cast<unsigned short&>(b);
    h.z = reinterpret_cast<unsigned short&>(c);
    h.w = reinterpret_cast<unsigned short&>(d);
    ((ushort4*)dst)[i] = h;
}

// ---------------------------------------------------------------------------
// Single-term fp16 GEMM via mma.sync: D[8192][NN] = Ah[8192][1024] @ Bh[1024][NN]
// 128x128 CTA tile, BK=64, 3-stage cp.async pipeline (32KB/stage), 8 warps
// (4m x 2n), warp tile 32x64, 64 MMAs per k-block, one sync per k-block.
// 2 CTAs/SM enforced.  MODE 0: fp16 scatter into qkvh.  MODE 1: fp32 write.
// ---------------------------------------------------------------------------
#define BK 64
#define NKB2 16                        // 1024 / 64
#define STAGES 3
#define ABUF 16384                     // 128 rows x 64 fp16 (128B rows)
#define BBUF 16384                     // 64 rows x 128 fp16 (256B rows)
#define STG_BYTES (ABUF + BBUF)        // 32768

template<int MODE, int NN>
__global__ __launch_bounds__(256, 2)
void tc_gemm(const unsigned short* __restrict__ Ah,
             const unsigned short* __restrict__ Bh, float* __restrict__ Cout)
{
    extern __shared__ __align__(1024) unsigned char gsm[];
    const uint32_t sbase = s2u(gsm);
    const int tid = threadIdx.x;
    const int lane = tid & 31, wid = tid >> 5;
    const int wm = wid & 3, wn = wid >> 2;
    const int bm = blockIdx.y * 128, bn = blockIdx.x * 128;

    const unsigned short* Abase = Ah + (size_t)bm * 1024;
    const unsigned short* Bbase = Bh + bn;

    auto load_stage = [&](int st, int kb) {
        uint32_t sb = sbase + st * STG_BYTES;
#pragma unroll
        for (int i = 0; i < 4; i++) {
            int id = i * 256 + tid;
            int r = id >> 3, c = id & 7;
            cpa16(sb + SW128(r * 128 + c * 16),
                  Abase + (size_t)r * 1024 + kb * BK + c * 8);
        }
#pragma unroll
        for (int i = 0; i < 4; i++) {
            int id = i * 256 + tid;
            int rk = id >> 4, cc = id & 15;
            cpa16(sb + ABUF + SWB(rk * 256 + cc * 16),
                  Bbase + (size_t)(kb * BK + rk) * NN + cc * 8);
        }
    };

    float acc[2][8][4];
#pragma unroll
    for (int mt = 0; mt < 2; mt++)
#pragma unroll
        for (int nt = 0; nt < 8; nt++)
#pragma unroll
            for (int q = 0; q < 4; q++) acc[mt][nt][q] = 0.f;

    load_stage(0, 0); cpa_commit();
    load_stage(1, 1); cpa_commit();

    const int a_lr = lane & 15;
    const int a_hk = (lane >> 4) << 4;

    for (int kb = 0; kb < NKB2; kb++) {
        const int cur = kb % STAGES;
        cpa_wait<1>();
        __syncthreads();
        if (kb + 2 < NKB2) load_stage((kb + 2) % STAGES, kb + 2);
        cpa_commit();

        uint32_t sb = sbase + cur * STG_BYTES;
#pragma unroll
        for (int ks = 0; ks < 4; ks++) {
            uint32_t afr[2][4];
#pragma unroll
            for (int mt = 0; mt < 2; mt++) {
                int r = wm * 32 + mt * 16 + a_lr;
                ldsm4(afr[mt], sb + SW128(r * 128 + ks * 32 + a_hk));
            }
            uint32_t bfr[8][2];
#pragma unroll
            for (int nt2 = 0; nt2 < 4; nt2++) {
                int kk = ks * 16 + a_lr;
                int nb = wn * 128 + nt2 * 32 + a_hk;
                uint32_t t[4];
                ldsm4t(t, sb + ABUF + SWB(kk * 256 + nb));
                bfr[nt2 * 2][0] = t[0]; bfr[nt2 * 2][1] = t[1];
                bfr[nt2 * 2 + 1][0] = t[2]; bfr[nt2 * 2 + 1][1] = t[3];
            }
#pragma unroll
            for (int mt = 0; mt < 2; mt++)
#pragma unroll
                for (int nt = 0; nt < 8; nt++)
                    mma16816(acc[mt][nt], afr[mt], bfr[nt]);
        }
    }

    const int gid = lane >> 2, tg = lane & 3;
#pragma unroll
    for (int mt = 0; mt < 2; mt++)
#pragma unroll
        for (int nt = 0; nt < 8; nt++) {
            int row0 = bm + wm * 32 + mt * 16 + gid;
            int col = bn + wn * 64 + nt * 8 + tg * 2;
#pragma unroll
            for (int half = 0; half < 2; half++) {
                int row = row0 + half * 8;
                float v0 = acc[mt][nt][half * 2], v1 = acc[mt][nt][half * 2 + 1];
                if (MODE == 0) {
                    int s = col >> 10, h = (col >> 6) & 15, d = col & 63;
                    int b = row >> 11, t = row & 2047;
                    size_t idx = (size_t)s * QKV_STRIDE +
                                 (((size_t)(b * Hn + h) * Tn + t) << 6) + d;
                    __half h0 = __float2half_rn(v0), h1 = __float2half_rn(v1);
                    *(uint32_t*)&qkvh[idx] =
                        (uint32_t)reinterpret_cast<unsigned short&>(h0) |
                        ((uint32_t)reinterpret_cast<unsigned short&>(h1) << 16);
                } else {
                    *(float2*)&Cout[(size_t)row * NN + col] = make_float2(v0, v1);
                }
            }
        }
}

// ---------------------------------------------------------------------------
// Tensor-core flash attention, single-term fp16 (Q, K, V, P all single fp16;
// fp32 accum).  256 threads = 8 warps; 128 q rows per block.  2 CTAs/SM.
// Softmax on raw logits (scale folded into exp); mask-free fast path for
// strictly-below-diagonal blocks; descending tile order for wave tail.
// ---------------------------------------------------------------------------
#define AQ_OFF 0                     // Q 16KB (128 rows x 128B)
#define AKV_OFF 16384                // 2 stages x (K 8KB + V 8KB)
#define APOS_OFF (16384 + 32768)     // 49152
#define ATTN_SMEM_SZ (16384 + 32768 + 512)

__global__ __launch_bounds__(256, 2)
void attn_mma(const int* __restrict__ pos)
{
    extern __shared__ __align__(1024) unsigned char am[];
    const uint32_t sb = s2u(am);
    const int tid = threadIdx.x, lane = tid & 31, wm = tid >> 5;   // wm 0..7
    const int b = blockIdx.y >> 4, h = blockIdx.y & 15;
    const int i0 = (15 - blockIdx.x) * 128;    // heavy tiles scheduled first

    const size_t bh_off = ((size_t)(b * Hn + h) * Tn) << 6;
    const unsigned short* Qhg = qkvh + bh_off + ((size_t)i0 << 6);
    const unsigned short* Khg = qkvh + (size_t)QKV_STRIDE + bh_off;
    const unsigned short* Vhg = qkvh + 2ull * QKV_STRIDE + bh_off;
    const int* posb = pos + b * Tn;

    // Q tile (128 rows) -> smem
#pragma unroll
    for (int i = 0; i < 2; i++) {
        int id = tid + i * 256;            // 0..511 ; 128 rows x 4 chunks? no:
    }
    // 128 rows x 8 chunks of 16B = 1024 chunks, 256 threads x 4
#pragma unroll
    for (int i = 0; i < 4; i++) {
        int id = tid + i * 256;
        int r = id >> 3, c = id & 7;
        cpa16(sb + AQ_OFF + SW128(r * 128 + c * 16), Qhg + (size_t)r * 64 + c * 8);
    }
    cpa_commit();

    auto load_kv = [&](int st, int j0) {
        uint32_t base = sb + AKV_OFF + st * 16384;
        const unsigned short* srcs[2] = {
            Khg + ((size_t)j0 << 6), Vhg + ((size_t)j0 << 6) };
#pragma unroll
        for (int buf = 0; buf < 2; buf++)
#pragma unroll
            for (int i = 0; i < 2; i++) {
                int id = tid + i * 256;      // 0..511
                int r = id >> 3, c = id & 7;
                cpa16(base + buf * 8192 + SW128(r * 128 + c * 16),
                      srcs[buf] + (size_t)r * 64 + c * 8);
            }
        if (tid < 16)
            cpa16(sb + APOS_OFF + st * 256 + tid * 16, posb + j0 + tid * 4);
    };

    load_kv(0, 0);
    cpa_commit();

    cpa_wait<1>();
    __syncthreads();
    const int a_lr = lane & 15, a_hk = (lane >> 4) << 4;
    uint32_t qfh[4][4];
#pragma unroll
    for (int ks = 0; ks < 4; ks++) {
        int r = wm * 16 + a_lr;
        ldsm4(qfh[ks], sb + AQ_OFF + SW128(r * 128 + ks * 32 + a_hk));
    }

    const int pq0 = posb[i0 + wm * 16 + (lane >> 2)];
    const int pq1 = posb[i0 + wm * 16 + (lane >> 2) + 8];
    const int pqmin = posb[i0];
    const int pqmax = posb[i0 + 127];
    const int jcol = 2 * (lane & 3);

    float m0 = -3e38f, m1 = -3e38f, l0 = 0.f, l1 = 0.f;
    float oacc[8][4];
#pragma unroll
    for (int nt = 0; nt < 8; nt++)
#pragma unroll
        for (int q = 0; q < 4; q++) oacc[nt][q] = 0.f;

    const float CS = 0.18033688011112042f;   // 0.125 * log2(e)

    int jb = 0, st = 0;
    for (;;) {
        int next = jb + 64;
        bool hn = (next < Tn) && (posb[next] <= pqmax);

        cpa_wait<0>();          // current stage fully resident
        __syncthreads();        // seals last iter's reads of stage st^1
        if (hn) { load_kv(st ^ 1, next); cpa_commit(); }

        const uint32_t kb_ = sb + AKV_OFF + st * 16384;
        const int* pkp = (const int*)(am + APOS_OFF + st * 256);

        float sacc[8][4];
#pragma unroll
        for (int nt = 0; nt < 8; nt++)
#pragma unroll
            for (int q = 0; q < 4; q++) sacc[nt][q] = 0.f;

#pragma unroll
        for (int ks = 0; ks < 4; ks++) {
            uint32_t kf[4][4];
            const int g = lane >> 3;
            const int krow = (g >> 1) * 8 + (lane & 7);
            const int kchk = ks * 32 + (g & 1) * 16;
#pragma unroll
            for (int call = 0; call < 4; call++) {
                uint32_t off = SW128((call * 16 + krow) * 128 + kchk);
                ldsm4(kf[call], kb_ + off);
            }
#pragma unroll
            for (int nt = 0; nt < 8; nt++) {
                const int c = nt >> 1, hf = (nt & 1) * 2;
                mma16816(sacc[nt], qfh[ks], &kf[c][hf]);
            }
        }

        // ---- online softmax on RAW logits; scale folded into exp ----
        const bool need_mask = (pkp[63] > pqmin);
        float mx0 = m0, mx1 = m1;
        if (need_mask) {
#pragma unroll
            for (int nt = 0; nt < 8; nt++) {
                int pk0 = pkp[nt * 8 + jcol], pk1 = pkp[nt * 8 + jcol + 1];
                float v0 = (pq0 < pk0) ? -3e38f : sacc[nt][0];
                float v1 = (pq0 < pk1) ? -3e38f : sacc[nt][1];
                float v2 = (pq1 < pk0) ? -3e38f : sacc[nt][2];
                float v3 = (pq1 < pk1) ? -3e38f : sacc[nt][3];
                sacc[nt][0] = v0; sacc[nt][1] = v1;
                sacc[nt][2] = v2; sacc[nt][3] = v3;
                mx0 = fmaxf(mx0, fmaxf(v0, v1));
                mx1 = fmaxf(mx1, fmaxf(v2, v3));
            }
        } else {
#pragma unroll
            for (int nt = 0; nt < 8; nt++) {
                mx0 = fmaxf(mx0, fmaxf(sacc[nt][0], sacc[nt][1]));
                mx1 = fmaxf(mx1, fmaxf(sacc[nt][2], sacc[nt][3]));
            }
        }
        mx0 = fmaxf(mx0, __shfl_xor_sync(0xffffffffu, mx0, 1));
        mx0 = fmaxf(mx0, __shfl_xor_sync(0xffffffffu, mx0, 2));
        mx1 = fmaxf(mx1, __shfl_xor_sync(0xffffffffu, mx1, 1));
        mx1 = fmaxf(mx1, __shfl_xor_sync(0xffffffffu, mx1, 2));
        float al0 = exp2f((m0 - mx0) * CS), al1 = exp2f((m1 - mx1) * CS);
        m0 = mx0; m1 = mx1;
        const float c0 = -mx0 * CS, c1 = -mx1 * CS;

        float s0 = 0.f, s1 = 0.f;
#pragma unroll
        for (int nt = 0; nt < 8; nt++) {
            float p0 = exp2f(fmaf(sacc[nt][0], CS, c0));
            float p1 = exp2f(fmaf(sacc[nt][1], CS, c0));
            float p2 = exp2f(fmaf(sacc[nt][2], CS, c1));
            float p3 = exp2f(fmaf(sacc[nt][3], CS, c1));
            sacc[nt][0] = p0; sacc[nt][1] = p1;
            sacc[nt][2] = p2; sacc[nt][3] = p3;
            s0 += p0 + p1; s1 += p2 + p3;
        }
        s0 += __shfl_xor_sync(0xffffffffu, s0, 1);
        s0 += __shfl_xor_sync(0xffffffffu, s0, 2);
        s1 += __shfl_xor_sync(0xffffffffu, s1, 1);
        s1 += __shfl_xor_sync(0xffffffffu, s1, 2);
        l0 = l0 * al0 + s0;
        l1 = l1 * al1 + s1;
#pragma unroll
        for (int nt = 0; nt < 8; nt++) {
            oacc[nt][0] *= al0; oacc[nt][1] *= al0;
            oacc[nt][2] *= al1; oacc[nt][3] *= al1;
        }

        const uint32_t vb = kb_ + 8192;
#pragma unroll
        for (int kt = 0; kt < 4; kt++) {
            uint32_t ph[4];
#pragma unroll
            for (int q = 0; q < 4; q++) {
                const float* src = (q < 2) ? sacc[2 * kt] : sacc[2 * kt + 1];
                float a = src[(q & 1) * 2], c = src[(q & 1) * 2 + 1];
                __half ha = __float2half_rn(a), hc = __float2half_rn(c);
                ph[q] = (uint32_t)reinterpret_cast<unsigned short&>(ha) |
                        ((uint32_t)reinterpret_cast<unsigned short&>(hc) << 16);
            }
            uint32_t vf[4][4];
#pragma unroll
            for (int call = 0; call < 4; call++) {
                uint32_t off = SW128((kt * 16 + a_lr) * 128 + call * 32 + a_hk);
                ldsm4t(vf[call], vb + off);
            }
#pragma unroll
            for (int nt = 0; nt < 8; nt++) {
                const int c = nt >> 1, hf = (nt & 1) * 2;
                mma16816(oacc[nt], ph, &vf[c][hf]);
            }
        }

        if (!hn) break;
        jb = next; st ^= 1;
    }

    // Epilogue: normalize, write single fp16 to ga_h
    float inv0 = 1.f / l0, inv1 = 1.f / l1;
    int t0r = i0 + wm * 16 + (lane >> 2);
#pragma unroll
    for (int nt = 0; nt < 8; nt++) {
        int col = h * 64 + nt * 8 + jcol;
#pragma unroll
        for (int half = 0; half < 2; half++) {
            int t = t0r + half * 8;
            float inv = half ? inv1 : inv0;
            float v0 = oacc[nt][half * 2] * inv;
            float v1 = oacc[nt][half * 2 + 1] * inv;
            __half h0 = __float2half_rn(v0), h1 = __float2half_rn(v1);
            size_t idx = ((size_t)b * Tn + t) * Dn + col;
            *(uint32_t*)&ga_h[idx] =
                (uint32_t)reinterpret_cast<unsigned short&>(h0) |
                ((uint32_t)reinterpret_cast<unsigned short&>(h1) << 16);
        }
    }
}

// ---------------------------------------------------------------------------
extern "C" void kernel_launch(void* const* d_in, const int* in_sizes, int n_in,
                              void* d_out, int out_size)
{
    const float* x   = (const float*)d_in[0];
    const int*   pos = (const int*)d_in[1];
    const float* Wq  = (const float*)d_in[2];
    const float* Wo  = (const float*)d_in[3];
    float* out = (float*)d_out;

    unsigned short *p_xh, *p_wq, *p_wo, *p_gah;
    cudaGetSymbolAddress((void**)&p_xh,  xa_h);
    cudaGetSymbolAddress((void**)&p_wq,  wq_h);
    cudaGetSymbolAddress((void**)&p_wo,  wo_h);
    cudaGetSymbolAddress((void**)&p_gah, ga_h);

    const int GEMM_SMEM = STAGES * STG_BYTES;   // 98304

    // 0) fused fp16 conversions (x, Wqkv, Wout in one launch)
    int nbx  = (Bn * Tn * Dn) / 4 / 256;     // 2048 blocks
    int nbwq = (3 * Dn * Dn) / 4 / 256;      // 3072 blocks
    int nbwo = (Dn * Dn) / 4 / 256;          // 1024 blocks
    conv_fused_kernel<<<nbx + nbwq + nbwo, 256>>>(x, p_xh, Wq, p_wq, Wo, p_wo,
                                                  nbx, nbwq, nbwo);

    // 1) QKV projection -> qkvh
    cudaFuncSetAttribute(tc_gemm<0, 3072>,
                         cudaFuncAttributeMaxDynamicSharedMemorySize, GEMM_SMEM);
    tc_gemm<0, 3072><<<dim3(24, 64), 256, GEMM_SMEM>>>(p_xh, p_wq, nullptr);

    // 2) tensor-core flash attention (128 q-rows / block) -> ga_h
    cudaFuncSetAttribute(attn_mma,
                         cudaFuncAttributeMaxDynamicSharedMemorySize, ATTN_SMEM_SZ);
    attn_mma<<<dim3(Tn / 128, Bn * Hn), 256, ATTN_SMEM_SZ>>>(pos);

    // 3) output projection -> d_out
    cudaFuncSetAttribute(tc_gemm<1, 1024>,
                         cudaFuncAttributeMaxDynamicSharedMemorySize, GEMM_SMEM);
    tc_gemm<1, 1024><<<dim3(8, 64), 256, GEMM_SMEM>>>(p_gah, p_wo, out);
}